// round 2
// baseline (speedup 1.0000x reference)
#include <cuda_runtime.h>

// Problem constants: x [1, 512, 64, 64] -> [C=512, N=4096], 32 groups, 16 heads, head_dim 32.
#define C_DIM 512
#define N_TOK 4096
#define NGRP  32
#define GSIZE 65536          // 16 channels * 4096 spatial, contiguous
#define HEADS 16
#define HDIM  32

// Scratch (device globals; no allocation allowed)
__device__ float g_qn[C_DIM * N_TOK];
__device__ float g_vn[C_DIM * N_TOK];
__device__ float g_q [C_DIM * N_TOK];
__device__ float g_k [C_DIM * N_TOK];
__device__ float g_v [C_DIM * N_TOK];
__device__ float g_ao[C_DIM * N_TOK];
__device__ float g_m1[NGRP], g_is1[NGRP], g_m2[NGRP], g_is2[NGRP];

// ---------------------------------------------------------------------------
// Block reduce (256 threads) of (sum, sumsq); result valid in thread 0.
// ---------------------------------------------------------------------------
__device__ __forceinline__ void blk_reduce2(float& s, float& sq, float* sh) {
    #pragma unroll
    for (int off = 16; off > 0; off >>= 1) {
        s  += __shfl_down_sync(0xffffffffu, s,  off);
        sq += __shfl_down_sync(0xffffffffu, sq, off);
    }
    int w = threadIdx.x >> 5, lane = threadIdx.x & 31;
    if (lane == 0) { sh[w] = s; sh[8 + w] = sq; }
    __syncthreads();
    if (threadIdx.x == 0) {
        float ts = 0.f, tq = 0.f;
        #pragma unroll
        for (int i = 0; i < 8; ++i) { ts += sh[i]; tq += sh[8 + i]; }
        s = ts; sq = tq;
    }
}

// ---------------------------------------------------------------------------
// GN1 stats on x: one block per group (group = 65536 contiguous floats)
// ---------------------------------------------------------------------------
__global__ __launch_bounds__(256) void gn_stats1(const float* __restrict__ x) {
    __shared__ float sh[16];
    int g = blockIdx.x;
    const float4* p = (const float4*)(x + (size_t)g * GSIZE);
    float s = 0.f, sq = 0.f;
    for (int i = threadIdx.x; i < GSIZE / 4; i += 256) {
        float4 v = p[i];
        s  += (v.x + v.y) + (v.z + v.w);
        sq += v.x * v.x + v.y * v.y + v.z * v.z + v.w * v.w;
    }
    blk_reduce2(s, sq, sh);
    if (threadIdx.x == 0) {
        float mean = s * (1.f / GSIZE);
        float var  = sq * (1.f / GSIZE) - mean * mean;
        g_m1[g] = mean;
        g_is1[g] = rsqrtf(var + 1e-6f);
    }
}

// ---------------------------------------------------------------------------
// Apply GN1 -> g_qn, and accumulate GN2 stats of qn in the same pass.
// One block per group.
// ---------------------------------------------------------------------------
__global__ __launch_bounds__(256) void gn_apply1_stats2(const float* __restrict__ x,
                                                        const float* __restrict__ w,
                                                        const float* __restrict__ b) {
    __shared__ float sh[16];
    int g = blockIdx.x;
    float m1 = g_m1[g], is1 = g_is1[g];
    const float4* px = (const float4*)(x + (size_t)g * GSIZE);
    float4* pq = (float4*)(g_qn + (size_t)g * GSIZE);
    float s = 0.f, sq = 0.f;
    for (int i = threadIdx.x; i < GSIZE / 4; i += 256) {
        int c = g * 16 + (i >> 10);            // 1024 float4 per channel
        float wc = w[c] * is1;
        float bc = b[c] - m1 * wc;             // val = x*wc + bc
        float4 v = px[i];
        v.x = v.x * wc + bc; v.y = v.y * wc + bc;
        v.z = v.z * wc + bc; v.w = v.w * wc + bc;
        pq[i] = v;
        s  += (v.x + v.y) + (v.z + v.w);
        sq += v.x * v.x + v.y * v.y + v.z * v.z + v.w * v.w;
    }
    blk_reduce2(s, sq, sh);
    if (threadIdx.x == 0) {
        float mean = s * (1.f / GSIZE);
        float var  = sq * (1.f / GSIZE) - mean * mean;
        g_m2[g] = mean;
        g_is2[g] = rsqrtf(var + 1e-6f);
    }
}

// ---------------------------------------------------------------------------
// Apply GN2: g_vn = GN(g_qn). Grid-stride elementwise.
// ---------------------------------------------------------------------------
__global__ __launch_bounds__(256) void gn_apply2(const float* __restrict__ w,
                                                 const float* __restrict__ b) {
    const float4* pq = (const float4*)g_qn;
    float4* pv = (float4*)g_vn;
    int total = (C_DIM * N_TOK) / 4;           // 524288 float4
    for (int i = blockIdx.x * blockDim.x + threadIdx.x; i < total;
         i += gridDim.x * blockDim.x) {
        int c = i >> 10;                       // channel
        int g = c >> 4;
        float wc = w[c] * g_is2[g];
        float bc = b[c] - g_m2[g] * wc;
        float4 v = pq[i];
        v.x = v.x * wc + bc; v.y = v.y * wc + bc;
        v.z = v.z * wc + bc; v.w = v.w * wc + bc;
        pv[i] = v;
    }
}

// ---------------------------------------------------------------------------
// fp32 GEMM: Out[m,n] = sum_k W[m,k]*X[k,n] + bias[m], m<512, n<4096, k=512.
// Optional fused epilogue: Out = (Out + resid) * (1/sqrt(2)).
// 128x128 tile, BK=16, 256 threads, 8x8 per thread (2x2 blocks of 4x4).
// ---------------------------------------------------------------------------
__global__ __launch_bounds__(256) void gemm512(const float* __restrict__ W,
                                               const float* __restrict__ X,
                                               const float* __restrict__ bias,
                                               const float* __restrict__ resid,
                                               float* __restrict__ Out,
                                               int do_resid) {
    __shared__ float As[16][132];   // As[k][m], padded
    __shared__ float Bs[16][132];   // Bs[k][n], padded

    int tid = threadIdx.x;
    int m0 = blockIdx.y * 128;
    int n0 = blockIdx.x * 128;
    int tr = tid >> 4, tc = tid & 15;

    float acc[8][8];
    #pragma unroll
    for (int i = 0; i < 8; ++i)
        #pragma unroll
        for (int j = 0; j < 8; ++j) acc[i][j] = 0.f;

    for (int k0 = 0; k0 < 512; k0 += 16) {
        // Load A tile (transpose W[m][k] -> As[k][m]); 512 float4 / 256 thr
        #pragma unroll
        for (int it = 0; it < 2; ++it) {
            int idx = tid + it * 256;          // 0..511
            int m = idx >> 2;
            int kq = (idx & 3) * 4;
            float4 a4 = *(const float4*)&W[(size_t)(m0 + m) * 512 + k0 + kq];
            As[kq + 0][m] = a4.x; As[kq + 1][m] = a4.y;
            As[kq + 2][m] = a4.z; As[kq + 3][m] = a4.w;
        }
        // Load B tile: Bs[k][n]
        #pragma unroll
        for (int it = 0; it < 2; ++it) {
            int idx = tid + it * 256;
            int k = idx >> 5;
            int nq = (idx & 31) * 4;
            *(float4*)&Bs[k][nq] =
                *(const float4*)&X[(size_t)(k0 + k) * N_TOK + n0 + nq];
        }
        __syncthreads();
        #pragma unroll
        for (int kk = 0; kk < 16; ++kk) {
            float a[8], b[8];
            *(float4*)&a[0] = *(const float4*)&As[kk][tr * 4];
            *(float4*)&a[4] = *(const float4*)&As[kk][64 + tr * 4];
            *(float4*)&b[0] = *(const float4*)&Bs[kk][tc * 4];
            *(float4*)&b[4] = *(const float4*)&Bs[kk][64 + tc * 4];
            #pragma unroll
            for (int i = 0; i < 8; ++i)
                #pragma unroll
                for (int j = 0; j < 8; ++j)
                    acc[i][j] += a[i] * b[j];
        }
        __syncthreads();
    }

    const float inv_sqrt2 = 0.70710678118654752f;
    #pragma unroll
    for (int i = 0; i < 8; ++i) {
        int m = m0 + ((i < 4) ? (tr * 4 + i) : (64 + tr * 4 + (i - 4)));
        float bm = bias[m];
        #pragma unroll
        for (int jh = 0; jh < 2; ++jh) {
            int n = n0 + tc * 4 + jh * 64;
            float4 r;
            r.x = acc[i][jh * 4 + 0] + bm;
            r.y = acc[i][jh * 4 + 1] + bm;
            r.z = acc[i][jh * 4 + 2] + bm;
            r.w = acc[i][jh * 4 + 3] + bm;
            if (do_resid) {
                float4 xr = *(const float4*)&resid[(size_t)m * N_TOK + n];
                r.x = (r.x + xr.x) * inv_sqrt2;
                r.y = (r.y + xr.y) * inv_sqrt2;
                r.z = (r.z + xr.z) * inv_sqrt2;
                r.w = (r.w + xr.w) * inv_sqrt2;
            }
            *(float4*)&Out[(size_t)m * N_TOK + n] = r;
        }
    }
}

// ---------------------------------------------------------------------------
// Flash attention: one query per thread, 16-key shared tiles.
// grid (16 qtiles, 16 heads), 256 threads. Layouts are [channel][token].
// ---------------------------------------------------------------------------
__global__ __launch_bounds__(256, 2) void attn_kernel() {
    __shared__ float Ks[HDIM * 16];   // Ks[d*16 + j]
    __shared__ float Vs[HDIM * 16];

    int tid = threadIdx.x;
    int h = blockIdx.y;
    int n = blockIdx.x * 256 + tid;

    const float* Qb = g_q + (size_t)(h * HDIM) * N_TOK;
    const float* Kb = g_k + (size_t)(h * HDIM) * N_TOK;
    const float* Vb = g_v + (size_t)(h * HDIM) * N_TOK;

    float q[HDIM], o[HDIM];
    #pragma unroll
    for (int d = 0; d < HDIM; ++d) {
        q[d] = Qb[(size_t)d * N_TOK + n];
        o[d] = 0.f;
    }
    float mrun = -1e30f, l = 0.f;
    const float scale = 0.17677669529663687f;   // 1/sqrt(32)

    int ld_j = tid & 15, ld_d = tid >> 4;       // 16x16 loaders, 2 elems each

    for (int m0 = 0; m0 < N_TOK; m0 += 16) {
        Ks[ld_d * 16 + ld_j]        = Kb[(size_t)ld_d * N_TOK + m0 + ld_j];
        Ks[(ld_d + 16) * 16 + ld_j] = Kb[(size_t)(ld_d + 16) * N_TOK + m0 + ld_j];
        Vs[ld_d * 16 + ld_j]        = Vb[(size_t)ld_d * N_TOK + m0 + ld_j];
        Vs[(ld_d + 16) * 16 + ld_j] = Vb[(size_t)(ld_d + 16) * N_TOK + m0 + ld_j];
        __syncthreads();

        float s[16];
        #pragma unroll
        for (int j = 0; j < 16; ++j) s[j] = 0.f;

        #pragma unroll
        for (int d = 0; d < HDIM; ++d) {
            float kv[16];
            *(float4*)&kv[0]  = *(const float4*)&Ks[d * 16 + 0];
            *(float4*)&kv[4]  = *(const float4*)&Ks[d * 16 + 4];
            *(float4*)&kv[8]  = *(const float4*)&Ks[d * 16 + 8];
            *(float4*)&kv[12] = *(const float4*)&Ks[d * 16 + 12];
            float qd = q[d];
            #pragma unroll
            for (int j = 0; j < 16; ++j) s[j] += qd * kv[j];
        }

        float tm = s[0] * scale;
        #pragma unroll
        for (int j = 0; j < 16; ++j) { s[j] *= scale; tm = fmaxf(tm, s[j]); }
        float mn = fmaxf(mrun, tm);
        float corr = __expf(mrun - mn);
        mrun = mn;
        l *= corr;
        #pragma unroll
        for (int d = 0; d < HDIM; ++d) o[d] *= corr;
        #pragma unroll
        for (int j = 0; j < 16; ++j) { s[j] = __expf(s[j] - mn); l += s[j]; }

        #pragma unroll
        for (int d = 0; d < HDIM; ++d) {
            float vv[16];
            *(float4*)&vv[0]  = *(const float4*)&Vs[d * 16 + 0];
            *(float4*)&vv[4]  = *(const float4*)&Vs[d * 16 + 4];
            *(float4*)&vv[8]  = *(const float4*)&Vs[d * 16 + 8];
            *(float4*)&vv[12] = *(const float4*)&Vs[d * 16 + 12];
            float acc = o[d];
            #pragma unroll
            for (int j = 0; j < 16; ++j) acc += s[j] * vv[j];
            o[d] = acc;
        }
        __syncthreads();
    }

    float invl = 1.f / l;
    float* Ob = g_ao + (size_t)(h * HDIM) * N_TOK;
    #pragma unroll
    for (int d = 0; d < HDIM; ++d)
        Ob[(size_t)d * N_TOK + n] = o[d] * invl;
}

// ---------------------------------------------------------------------------
// Launch
// ---------------------------------------------------------------------------
extern "C" void kernel_launch(void* const* d_in, const int* in_sizes, int n_in,
                              void* d_out, int out_size) {
    const float* x   = (const float*)d_in[0];
    const float* gnw = (const float*)d_in[1];
    const float* gnb = (const float*)d_in[2];
    const float* wq  = (const float*)d_in[3];
    const float* bq  = (const float*)d_in[4];
    const float* wk  = (const float*)d_in[5];
    const float* bk  = (const float*)d_in[6];
    const float* wv  = (const float*)d_in[7];
    const float* bv  = (const float*)d_in[8];
    const float* wo  = (const float*)d_in[9];
    const float* bo  = (const float*)d_in[10];
    float* out = (float*)d_out;

    float *qn, *vn, *qb, *kb, *vb, *ao;
    cudaGetSymbolAddress((void**)&qn, g_qn);
    cudaGetSymbolAddress((void**)&vn, g_vn);
    cudaGetSymbolAddress((void**)&qb, g_q);
    cudaGetSymbolAddress((void**)&kb, g_k);
    cudaGetSymbolAddress((void**)&vb, g_v);
    cudaGetSymbolAddress((void**)&ao, g_ao);

    gn_stats1<<<NGRP, 256>>>(x);
    gn_apply1_stats2<<<NGRP, 256>>>(x, gnw, gnb);
    gn_apply2<<<512, 256>>>(gnw, gnb);

    dim3 gg(N_TOK / 128, C_DIM / 128);   // (32, 4)
    gemm512<<<gg, 256>>>(wq, qn, bq, nullptr, qb, 0);
    gemm512<<<gg, 256>>>(wk, vn, bk, nullptr, kb, 0);
    gemm512<<<gg, 256>>>(wv, vn, bv, nullptr, vb, 0);

    dim3 ag(N_TOK / 256, HEADS);         // (16, 16)
    attn_kernel<<<ag, 256>>>();

    gemm512<<<gg, 256>>>(wo, ao, bo, x, out, 1);
}

// round 3
// speedup vs baseline: 3.0664x; 3.0664x over previous
#include <cuda_runtime.h>

#define C_DIM 512
#define N_TOK 4096
#define NGRP  32
#define GSIZE 65536
#define HEADS 16
#define HDIM  32

// Scratch
__device__ float g_qn [C_DIM * N_TOK];      // GN1(x), channel-major [c][n]
__device__ float g_vn [C_DIM * N_TOK];      // GN2(qn), channel-major
__device__ float g_qt [N_TOK * C_DIM];      // Q, token-major [n][c]
__device__ float g_kt [N_TOK * C_DIM];      // K, token-major
__device__ float g_v  [C_DIM * N_TOK];      // V, channel-major [c][n]
__device__ float g_aot[N_TOK * C_DIM];      // attention out, token-major
__device__ float g_m1[NGRP], g_is1[NGRP], g_m2[NGRP], g_is2[NGRP];

// ---------------------------------------------------------------------------
// tf32 helpers
// ---------------------------------------------------------------------------
__device__ __forceinline__ unsigned f2tf32(float f) {
    unsigned u;
    asm("cvt.rna.tf32.f32 %0, %1;" : "=r"(u) : "f"(f));
    return u;
}
__device__ __forceinline__ void mma_tf32(float* d, const unsigned* a, const unsigned* b) {
    asm volatile(
        "mma.sync.aligned.m16n8k8.row.col.f32.tf32.tf32.f32 "
        "{%0,%1,%2,%3}, {%4,%5,%6,%7}, {%8,%9}, {%0,%1,%2,%3};"
        : "+f"(d[0]), "+f"(d[1]), "+f"(d[2]), "+f"(d[3])
        : "r"(a[0]), "r"(a[1]), "r"(a[2]), "r"(a[3]), "r"(b[0]), "r"(b[1]));
}

// ---------------------------------------------------------------------------
// GroupNorm (unchanged from fp32 baseline)
// ---------------------------------------------------------------------------
__device__ __forceinline__ void blk_reduce2(float& s, float& sq, float* sh) {
    #pragma unroll
    for (int off = 16; off > 0; off >>= 1) {
        s  += __shfl_down_sync(0xffffffffu, s,  off);
        sq += __shfl_down_sync(0xffffffffu, sq, off);
    }
    int w = threadIdx.x >> 5, lane = threadIdx.x & 31;
    if (lane == 0) { sh[w] = s; sh[8 + w] = sq; }
    __syncthreads();
    if (threadIdx.x == 0) {
        float ts = 0.f, tq = 0.f;
        #pragma unroll
        for (int i = 0; i < 8; ++i) { ts += sh[i]; tq += sh[8 + i]; }
        s = ts; sq = tq;
    }
}

__global__ __launch_bounds__(256) void gn_stats1(const float* __restrict__ x) {
    __shared__ float sh[16];
    int g = blockIdx.x;
    const float4* p = (const float4*)(x + (size_t)g * GSIZE);
    float s = 0.f, sq = 0.f;
    for (int i = threadIdx.x; i < GSIZE / 4; i += 256) {
        float4 v = p[i];
        s  += (v.x + v.y) + (v.z + v.w);
        sq += v.x * v.x + v.y * v.y + v.z * v.z + v.w * v.w;
    }
    blk_reduce2(s, sq, sh);
    if (threadIdx.x == 0) {
        float mean = s * (1.f / GSIZE);
        float var  = sq * (1.f / GSIZE) - mean * mean;
        g_m1[g] = mean;
        g_is1[g] = rsqrtf(var + 1e-6f);
    }
}

__global__ __launch_bounds__(256) void gn_apply1_stats2(const float* __restrict__ x,
                                                        const float* __restrict__ w,
                                                        const float* __restrict__ b) {
    __shared__ float sh[16];
    int g = blockIdx.x;
    float m1 = g_m1[g], is1 = g_is1[g];
    const float4* px = (const float4*)(x + (size_t)g * GSIZE);
    float4* pq = (float4*)(g_qn + (size_t)g * GSIZE);
    float s = 0.f, sq = 0.f;
    for (int i = threadIdx.x; i < GSIZE / 4; i += 256) {
        int c = g * 16 + (i >> 10);
        float wc = w[c] * is1;
        float bc = b[c] - m1 * wc;
        float4 v = px[i];
        v.x = v.x * wc + bc; v.y = v.y * wc + bc;
        v.z = v.z * wc + bc; v.w = v.w * wc + bc;
        pq[i] = v;
        s  += (v.x + v.y) + (v.z + v.w);
        sq += v.x * v.x + v.y * v.y + v.z * v.z + v.w * v.w;
    }
    blk_reduce2(s, sq, sh);
    if (threadIdx.x == 0) {
        float mean = s * (1.f / GSIZE);
        float var  = sq * (1.f / GSIZE) - mean * mean;
        g_m2[g] = mean;
        g_is2[g] = rsqrtf(var + 1e-6f);
    }
}

__global__ __launch_bounds__(256) void gn_apply2(const float* __restrict__ w,
                                                 const float* __restrict__ b) {
    const float4* pq = (const float4*)g_qn;
    float4* pv = (float4*)g_vn;
    int total = (C_DIM * N_TOK) / 4;
    for (int i = blockIdx.x * blockDim.x + threadIdx.x; i < total;
         i += gridDim.x * blockDim.x) {
        int c = i >> 10;
        int g = c >> 4;
        float wc = w[c] * g_is2[g];
        float bc = b[c] - g_m2[g] * wc;
        float4 v = pq[i];
        v.x = v.x * wc + bc; v.y = v.y * wc + bc;
        v.z = v.z * wc + bc; v.w = v.w * wc + bc;
        pv[i] = v;
    }
}

// ---------------------------------------------------------------------------
// tf32 tensor-core GEMM: Out = W[512,512] * X[512-k, 4096-n] + bias.
// BL=0: X gmem layout [k][n] (channel-major activations)
// BL=1: X gmem layout [n][k] (token-major activations)
// OUTT=0: Out channel-major [m][4096];  OUTT=1: Out token-major [n][512]
// RES=1 (requires OUTT=0): Out = (Out + resid)*inv_sqrt2
// Block tile 128(m) x 128(n), BK=32, 256 threads, warp tile 64x32.
// ---------------------------------------------------------------------------
template<int BL, int OUTT, int RES>
__global__ __launch_bounds__(256) void gemm_tc(const float* __restrict__ W,
                                               const float* __restrict__ X,
                                               const float* __restrict__ bias,
                                               const float* __restrict__ resid,
                                               float* __restrict__ Out) {
    __shared__ unsigned As[128 * 36];                     // [m][k], pad 36
    __shared__ unsigned Bs[(BL == 0) ? 32 * 136 : 128 * 36];

    int tid = threadIdx.x;
    int warp = tid >> 5, lane = tid & 31;
    int g = lane >> 2, qq = lane & 3;
    int wm = warp >> 2, wn = warp & 3;                    // 2 x 4 warps
    int m0 = blockIdx.y * 128;
    int n0 = blockIdx.x * 128;

    float acc[4][4][4];
    #pragma unroll
    for (int i = 0; i < 4; ++i)
        #pragma unroll
        for (int j = 0; j < 4; ++j)
            #pragma unroll
            for (int r = 0; r < 4; ++r) acc[i][j][r] = 0.f;

    for (int k0 = 0; k0 < 512; k0 += 32) {
        // A tile: W[m0..m0+127][k0..k0+31]  -> As[m][k]
        #pragma unroll
        for (int it = 0; it < 4; ++it) {
            int idx = tid + it * 256;
            int m = idx >> 3, q = idx & 7;
            float4 v = *(const float4*)&W[(size_t)(m0 + m) * 512 + k0 + 4 * q];
            uint4 u = make_uint4(f2tf32(v.x), f2tf32(v.y), f2tf32(v.z), f2tf32(v.w));
            *(uint4*)&As[m * 36 + 4 * q] = u;
        }
        // B tile
        if (BL == 0) {
            #pragma unroll
            for (int it = 0; it < 4; ++it) {
                int idx = tid + it * 256;
                int k = idx >> 5, q = idx & 31;
                float4 v = *(const float4*)&X[(size_t)(k0 + k) * N_TOK + n0 + 4 * q];
                uint4 u = make_uint4(f2tf32(v.x), f2tf32(v.y), f2tf32(v.z), f2tf32(v.w));
                *(uint4*)&Bs[k * 136 + 4 * q] = u;
            }
        } else {
            #pragma unroll
            for (int it = 0; it < 4; ++it) {
                int idx = tid + it * 256;
                int n = idx >> 3, q = idx & 7;
                float4 v = *(const float4*)&X[(size_t)(n0 + n) * 512 + k0 + 4 * q];
                uint4 u = make_uint4(f2tf32(v.x), f2tf32(v.y), f2tf32(v.z), f2tf32(v.w));
                *(uint4*)&Bs[n * 36 + 4 * q] = u;
            }
        }
        __syncthreads();

        #pragma unroll
        for (int kk = 0; kk < 4; ++kk) {
            unsigned a[4][4], b[4][2];
            #pragma unroll
            for (int mi = 0; mi < 4; ++mi) {
                int r = wm * 64 + mi * 16 + g;
                a[mi][0] = As[r * 36 + kk * 8 + qq];
                a[mi][1] = As[(r + 8) * 36 + kk * 8 + qq];
                a[mi][2] = As[r * 36 + kk * 8 + qq + 4];
                a[mi][3] = As[(r + 8) * 36 + kk * 8 + qq + 4];
            }
            #pragma unroll
            for (int ni = 0; ni < 4; ++ni) {
                int n = wn * 32 + ni * 8 + g;
                if (BL == 0) {
                    b[ni][0] = Bs[(kk * 8 + qq) * 136 + n];
                    b[ni][1] = Bs[(kk * 8 + qq + 4) * 136 + n];
                } else {
                    b[ni][0] = Bs[n * 36 + kk * 8 + qq];
                    b[ni][1] = Bs[n * 36 + kk * 8 + qq + 4];
                }
            }
            #pragma unroll
            for (int mi = 0; mi < 4; ++mi)
                #pragma unroll
                for (int ni = 0; ni < 4; ++ni)
                    mma_tf32(acc[mi][ni], a[mi], b[ni]);
        }
        __syncthreads();
    }

    const float IS2 = 0.70710678118654752f;
    #pragma unroll
    for (int mi = 0; mi < 4; ++mi) {
        int r = m0 + wm * 64 + mi * 16 + g;
        float b0 = bias[r], b8 = bias[r + 8];
        #pragma unroll
        for (int ni = 0; ni < 4; ++ni) {
            int n = n0 + wn * 32 + ni * 8 + 2 * qq;
            float c0 = acc[mi][ni][0] + b0, c1 = acc[mi][ni][1] + b0;
            float c2 = acc[mi][ni][2] + b8, c3 = acc[mi][ni][3] + b8;
            if (OUTT == 0) {
                if (RES) {
                    float2 r0 = *(const float2*)&resid[(size_t)r * N_TOK + n];
                    float2 r8 = *(const float2*)&resid[(size_t)(r + 8) * N_TOK + n];
                    c0 = (c0 + r0.x) * IS2; c1 = (c1 + r0.y) * IS2;
                    c2 = (c2 + r8.x) * IS2; c3 = (c3 + r8.y) * IS2;
                }
                *(float2*)&Out[(size_t)r * N_TOK + n] = make_float2(c0, c1);
                *(float2*)&Out[(size_t)(r + 8) * N_TOK + n] = make_float2(c2, c3);
            } else {
                Out[(size_t)n * 512 + r] = c0;
                Out[(size_t)(n + 1) * 512 + r] = c1;
                Out[(size_t)n * 512 + r + 8] = c2;
                Out[(size_t)(n + 1) * 512 + r + 8] = c3;
            }
        }
    }
}

// ---------------------------------------------------------------------------
// Flash attention, tf32 tensor cores.
// Block = (64 queries) x head, 128 threads (4 warps, 16 queries each).
// Q/K token-major [tok][512]; V channel-major [c][tok]; out token-major.
// ---------------------------------------------------------------------------
__global__ __launch_bounds__(128) void attn_tc(const float* __restrict__ Qt,
                                               const float* __restrict__ Kt,
                                               const float* __restrict__ V,
                                               float* __restrict__ Ot) {
    __shared__ unsigned Ks[64 * 36];       // [key][d], pad 36
    __shared__ unsigned Vs[32 * 68];       // [d][key], pad 68
    __shared__ unsigned Ps[4][16 * 72];    // per-warp P [qrow][key], pad 72

    int tid = threadIdx.x;
    int w = tid >> 5, lane = tid & 31;
    int g = lane >> 2, qq = lane & 3;
    int h = blockIdx.y;
    int qrow = blockIdx.x * 64 + w * 16;
    const float scale = 0.17677669529663687f;   // 1/sqrt(32)

    // Q fragments resident in registers, scale folded in
    unsigned qa[4][4];
    #pragma unroll
    for (int kk = 0; kk < 4; ++kk) {
        const float* qp = &Qt[(size_t)(qrow + g) * 512 + h * HDIM + kk * 8 + qq];
        qa[kk][0] = f2tf32(scale * qp[0]);
        qa[kk][1] = f2tf32(scale * qp[8 * 512]);
        qa[kk][2] = f2tf32(scale * qp[4]);
        qa[kk][3] = f2tf32(scale * qp[8 * 512 + 4]);
    }

    float o[4][4];
    #pragma unroll
    for (int i = 0; i < 4; ++i)
        #pragma unroll
        for (int j = 0; j < 4; ++j) o[i][j] = 0.f;
    float m_a = -1e30f, m_b = -1e30f, l_a = 0.f, l_b = 0.f;

    for (int kt = 0; kt < N_TOK; kt += 64) {
        // K tile: Kt[kt+key][h*32 + d] -> Ks[key][d]
        #pragma unroll
        for (int it = 0; it < 4; ++it) {
            int idx = tid + it * 128;
            int key = idx >> 3, q = idx & 7;
            float4 v = *(const float4*)&Kt[(size_t)(kt + key) * 512 + h * HDIM + 4 * q];
            uint4 u = make_uint4(f2tf32(v.x), f2tf32(v.y), f2tf32(v.z), f2tf32(v.w));
            *(uint4*)&Ks[key * 36 + 4 * q] = u;
        }
        // V tile: V[h*32+d][kt+key] -> Vs[d][key]
        #pragma unroll
        for (int it = 0; it < 4; ++it) {
            int idx = tid + it * 128;
            int d = idx >> 4, q = idx & 15;
            float4 v = *(const float4*)&V[(size_t)(h * HDIM + d) * N_TOK + kt + 4 * q];
            uint4 u = make_uint4(f2tf32(v.x), f2tf32(v.y), f2tf32(v.z), f2tf32(v.w));
            *(uint4*)&Vs[d * 68 + 4 * q] = u;
        }
        __syncthreads();

        // S = Q*K^T  (16 x 64 per warp)
        float s[8][4];
        #pragma unroll
        for (int nj = 0; nj < 8; ++nj) {
            s[nj][0] = s[nj][1] = s[nj][2] = s[nj][3] = 0.f;
            #pragma unroll
            for (int kk = 0; kk < 4; ++kk) {
                unsigned b[2];
                b[0] = Ks[(nj * 8 + g) * 36 + kk * 8 + qq];
                b[1] = Ks[(nj * 8 + g) * 36 + kk * 8 + qq + 4];
                mma_tf32(s[nj], qa[kk], b);
            }
        }

        // online softmax (rows g and g+8; row reduce across quad lanes)
        float mxa = -1e30f, mxb = -1e30f;
        #pragma unroll
        for (int nj = 0; nj < 8; ++nj) {
            mxa = fmaxf(mxa, fmaxf(s[nj][0], s[nj][1]));
            mxb = fmaxf(mxb, fmaxf(s[nj][2], s[nj][3]));
        }
        mxa = fmaxf(mxa, __shfl_xor_sync(0xffffffffu, mxa, 1));
        mxa = fmaxf(mxa, __shfl_xor_sync(0xffffffffu, mxa, 2));
        mxb = fmaxf(mxb, __shfl_xor_sync(0xffffffffu, mxb, 1));
        mxb = fmaxf(mxb, __shfl_xor_sync(0xffffffffu, mxb, 2));
        float mna = fmaxf(m_a, mxa), mnb = fmaxf(m_b, mxb);
        float ca = __expf(m_a - mna), cb = __expf(m_b - mnb);
        m_a = mna; m_b = mnb;
        l_a *= ca; l_b *= cb;
        #pragma unroll
        for (int nd = 0; nd < 4; ++nd) {
            o[nd][0] *= ca; o[nd][1] *= ca;
            o[nd][2] *= cb; o[nd][3] *= cb;
        }
        unsigned* ps = Ps[w];
        #pragma unroll
        for (int nj = 0; nj < 8; ++nj) {
            float e0 = __expf(s[nj][0] - mna), e1 = __expf(s[nj][1] - mna);
            float e2 = __expf(s[nj][2] - mnb), e3 = __expf(s[nj][3] - mnb);
            l_a += e0 + e1; l_b += e2 + e3;
            *(uint2*)&ps[g * 72 + nj * 8 + 2 * qq]       = make_uint2(f2tf32(e0), f2tf32(e1));
            *(uint2*)&ps[(g + 8) * 72 + nj * 8 + 2 * qq] = make_uint2(f2tf32(e2), f2tf32(e3));
        }
        __syncwarp();

        // O += P * V   (16 x 32 per warp, K = 64 keys)
        #pragma unroll
        for (int kk = 0; kk < 8; ++kk) {
            unsigned a[4];
            a[0] = ps[g * 72 + kk * 8 + qq];
            a[1] = ps[(g + 8) * 72 + kk * 8 + qq];
            a[2] = ps[g * 72 + kk * 8 + qq + 4];
            a[3] = ps[(g + 8) * 72 + kk * 8 + qq + 4];
            #pragma unroll
            for (int nd = 0; nd < 4; ++nd) {
                unsigned b[2];
                b[0] = Vs[(nd * 8 + g) * 68 + kk * 8 + qq];
                b[1] = Vs[(nd * 8 + g) * 68 + kk * 8 + qq + 4];
                mma_tf32(o[nd], a, b);
            }
        }
        __syncthreads();
    }

    l_a += __shfl_xor_sync(0xffffffffu, l_a, 1);
    l_a += __shfl_xor_sync(0xffffffffu, l_a, 2);
    l_b += __shfl_xor_sync(0xffffffffu, l_b, 1);
    l_b += __shfl_xor_sync(0xffffffffu, l_b, 2);
    float ia = 1.f / l_a, ib = 1.f / l_b;

    #pragma unroll
    for (int nd = 0; nd < 4; ++nd) {
        int d = h * HDIM + nd * 8 + 2 * qq;
        *(float2*)&Ot[(size_t)(qrow + g) * 512 + d] =
            make_float2(o[nd][0] * ia, o[nd][1] * ia);
        *(float2*)&Ot[(size_t)(qrow + 8 + g) * 512 + d] =
            make_float2(o[nd][2] * ib, o[nd][3] * ib);
    }
}

// ---------------------------------------------------------------------------
// Launch
// ---------------------------------------------------------------------------
extern "C" void kernel_launch(void* const* d_in, const int* in_sizes, int n_in,
                              void* d_out, int out_size) {
    const float* x   = (const float*)d_in[0];
    const float* gnw = (const float*)d_in[1];
    const float* gnb = (const float*)d_in[2];
    const float* wq  = (const float*)d_in[3];
    const float* bq  = (const float*)d_in[4];
    const float* wk  = (const float*)d_in[5];
    const float* bk  = (const float*)d_in[6];
    const float* wv  = (const float*)d_in[7];
    const float* bv  = (const float*)d_in[8];
    const float* wo  = (const float*)d_in[9];
    const float* bo  = (const float*)d_in[10];
    float* out = (float*)d_out;

    float *qn, *vn, *qt, *kt, *vb, *aot;
    cudaGetSymbolAddress((void**)&qn,  g_qn);
    cudaGetSymbolAddress((void**)&vn,  g_vn);
    cudaGetSymbolAddress((void**)&qt,  g_qt);
    cudaGetSymbolAddress((void**)&kt,  g_kt);
    cudaGetSymbolAddress((void**)&vb,  g_v);
    cudaGetSymbolAddress((void**)&aot, g_aot);

    gn_stats1<<<NGRP, 256>>>(x);
    gn_apply1_stats2<<<NGRP, 256>>>(x, gnw, gnb);
    gn_apply2<<<512, 256>>>(gnw, gnb);

    dim3 gg(N_TOK / 128, C_DIM / 128);   // (32, 4)
    // Q, K: channel-major input, token-major output
    gemm_tc<0, 1, 0><<<gg, 256>>>(wq, qn, bq, nullptr, qt);
    gemm_tc<0, 1, 0><<<gg, 256>>>(wk, vn, bk, nullptr, kt);
    // V: channel-major input and output
    gemm_tc<0, 0, 0><<<gg, 256>>>(wv, vn, bv, nullptr, vb);

    dim3 ag(N_TOK / 64, HEADS);          // (64, 16)
    attn_tc<<<ag, 128>>>(qt, kt, vb, aot);

    // final conv: token-major input, channel-major output, fused residual
    gemm_tc<1, 0, 1><<<gg, 256>>>(wo, aot, bo, x, out);
}

// round 4
// speedup vs baseline: 4.0251x; 1.3126x over previous
#include <cuda_runtime.h>

#define C_DIM 512
#define N_TOK 4096
#define HEADS 16
#define HDIM  32

// ---------------- scratch (device globals) ----------------
__device__ float g_qn [C_DIM * N_TOK];      // GN1(x)  rounded, channel-major
__device__ float g_vn [C_DIM * N_TOK];      // GN2(qn) rounded, channel-major
__device__ float g_qt [N_TOK * C_DIM];      // Q rounded, token-major
__device__ float g_kt [N_TOK * C_DIM];      // K rounded, token-major
__device__ float g_v  [C_DIM * N_TOK];      // V rounded, channel-major
__device__ float g_aot[N_TOK * C_DIM];      // attn out rounded, token-major
__device__ float g_w4 [4 * C_DIM * C_DIM];  // rounded weights: wq,wk,wv,wo
__device__ float g_cs[C_DIM], g_cq[C_DIM];              // per-channel sum / sumsq
__device__ float g_a1[C_DIM], g_c1[C_DIM];              // qn = a1*x + c1
__device__ float g_av[C_DIM], g_cv[C_DIM];              // vn = av*x + cv

// ---------------- helpers ----------------
__device__ __forceinline__ unsigned f2tf32(float f) {
    unsigned u; asm("cvt.rna.tf32.f32 %0, %1;" : "=r"(u) : "f"(f)); return u;
}
__device__ __forceinline__ float rnd(float f) { return __uint_as_float(f2tf32(f)); }
__device__ __forceinline__ float ex2(float x) {
    float r; asm("ex2.approx.ftz.f32 %0, %1;" : "=f"(r) : "f"(x)); return r;
}
__device__ __forceinline__ void mma_tf32(float* d, const unsigned* a, const unsigned* b) {
    asm volatile(
        "mma.sync.aligned.m16n8k8.row.col.f32.tf32.tf32.f32 "
        "{%0,%1,%2,%3}, {%4,%5,%6,%7}, {%8,%9}, {%0,%1,%2,%3};"
        : "+f"(d[0]), "+f"(d[1]), "+f"(d[2]), "+f"(d[3])
        : "r"(a[0]), "r"(a[1]), "r"(a[2]), "r"(a[3]), "r"(b[0]), "r"(b[1]));
}
__device__ __forceinline__ void cp16(void* smem, const void* gmem) {
    unsigned sa = (unsigned)__cvta_generic_to_shared(smem);
    asm volatile("cp.async.cg.shared.global [%0], [%1], 16;" :: "r"(sa), "l"(gmem) : "memory");
}
#define CP_COMMIT asm volatile("cp.async.commit_group;" ::: "memory")
#define CP_WAIT1  asm volatile("cp.async.wait_group 1;" ::: "memory")
#define CP_WAIT0  asm volatile("cp.async.wait_group 0;" ::: "memory")

// ---------------- GroupNorm: per-channel stats ----------------
__device__ __forceinline__ void blk_reduce2(float& s, float& sq, float* sh) {
    #pragma unroll
    for (int off = 16; off > 0; off >>= 1) {
        s  += __shfl_down_sync(0xffffffffu, s,  off);
        sq += __shfl_down_sync(0xffffffffu, sq, off);
    }
    int w = threadIdx.x >> 5, lane = threadIdx.x & 31;
    if (lane == 0) { sh[w] = s; sh[8 + w] = sq; }
    __syncthreads();
    if (threadIdx.x == 0) {
        float ts = 0.f, tq = 0.f;
        #pragma unroll
        for (int i = 0; i < 8; ++i) { ts += sh[i]; tq += sh[8 + i]; }
        s = ts; sq = tq;
    }
}

__global__ __launch_bounds__(256) void chan_stats(const float* __restrict__ x) {
    __shared__ float sh[16];
    int c = blockIdx.x;
    const float4* p = (const float4*)(x + (size_t)c * N_TOK);
    float s = 0.f, sq = 0.f;
    #pragma unroll
    for (int i = threadIdx.x; i < N_TOK / 4; i += 256) {
        float4 v = p[i];
        s  += (v.x + v.y) + (v.z + v.w);
        sq += v.x * v.x + v.y * v.y + v.z * v.z + v.w * v.w;
    }
    blk_reduce2(s, sq, sh);
    if (threadIdx.x == 0) { g_cs[c] = s; g_cq[c] = sq; }
}

// one block, 32 threads: derive both GN affines analytically
__global__ void gn_finalize(const float* __restrict__ w, const float* __restrict__ b) {
    int g = threadIdx.x;
    if (g >= 32) return;
    const float inv = 1.f / (float)N_TOK;
    float m1 = 0.f, E1 = 0.f;
    #pragma unroll
    for (int c = 0; c < 16; ++c) {
        int ch = g * 16 + c;
        m1 += g_cs[ch] * inv;
        E1 += g_cq[ch] * inv;
    }
    m1 *= (1.f / 16.f); E1 *= (1.f / 16.f);
    float is1 = rsqrtf(E1 - m1 * m1 + 1e-6f);
    float m2 = 0.f, E2 = 0.f;
    #pragma unroll
    for (int c = 0; c < 16; ++c) {
        int ch = g * 16 + c;
        float mc = g_cs[ch] * inv, Ec = g_cq[ch] * inv;
        float a1 = w[ch] * is1;
        float c1 = b[ch] - m1 * a1;
        g_a1[ch] = a1; g_c1[ch] = c1;
        m2 += a1 * mc + c1;
        E2 += a1 * a1 * Ec + 2.f * a1 * c1 * mc + c1 * c1;
    }
    m2 *= (1.f / 16.f); E2 *= (1.f / 16.f);
    float is2 = rsqrtf(E2 - m2 * m2 + 1e-6f);
    #pragma unroll
    for (int c = 0; c < 16; ++c) {
        int ch = g * 16 + c;
        float a2 = w[ch] * is2;
        float c2 = b[ch] - m2 * a2;
        g_av[ch] = a2 * g_a1[ch];
        g_cv[ch] = a2 * g_c1[ch] + c2;
    }
}

// single pass: qn and vn (both tf32-rounded) from x
__global__ __launch_bounds__(256) void apply_both(const float* __restrict__ x) {
    const float4* px = (const float4*)x;
    float4* pq = (float4*)g_qn;
    float4* pv = (float4*)g_vn;
    int total = (C_DIM * N_TOK) / 4;
    for (int i = blockIdx.x * 256 + threadIdx.x; i < total; i += gridDim.x * 256) {
        int c = i >> 10;
        float aq = g_a1[c], cq = g_c1[c], av = g_av[c], cv = g_cv[c];
        float4 v = px[i];
        float4 q4, v4;
        q4.x = rnd(v.x * aq + cq); q4.y = rnd(v.y * aq + cq);
        q4.z = rnd(v.z * aq + cq); q4.w = rnd(v.w * aq + cq);
        v4.x = rnd(v.x * av + cv); v4.y = rnd(v.y * av + cv);
        v4.z = rnd(v.z * av + cv); v4.w = rnd(v.w * av + cv);
        pq[i] = q4; pv[i] = v4;
    }
}

// pre-round the 4 weight matrices into g_w4
__global__ __launch_bounds__(256) void round_w(const float* __restrict__ wq,
                                               const float* __restrict__ wk,
                                               const float* __restrict__ wv,
                                               const float* __restrict__ wo) {
    float4* dst = (float4*)g_w4;
    int total = 4 * C_DIM * C_DIM / 4;        // 262144 float4
    for (int i = blockIdx.x * 256 + threadIdx.x; i < total; i += gridDim.x * 256) {
        int sel = i >> 16, loc = i & 65535;
        const float4* src = (const float4*)(sel == 0 ? wq : sel == 1 ? wk : sel == 2 ? wv : wo);
        float4 v = src[loc];
        v.x = rnd(v.x); v.y = rnd(v.y); v.z = rnd(v.z); v.w = rnd(v.w);
        dst[i] = v;
    }
}

// ---------------------------------------------------------------------------
// tf32 GEMM, cp.async double-buffered. Out = W*X + bias.
// QKV=1: z=blockIdx.z picks {wq*qn->qt, wk*vn->kt, wv*vn->v}; epilogue rounds.
// QKV=0: wo * aot(token-major) + bo, + residual, * 1/sqrt(2) -> d_out.
// 128x128 tile, BK=32, 256 threads, warp tile 64x32.
// ---------------------------------------------------------------------------
template<int BL, int QKV>
__global__ __launch_bounds__(256) void gemm_tc(const float* __restrict__ b0,
                                               const float* __restrict__ b1,
                                               const float* __restrict__ b2,
                                               const float* __restrict__ resid,
                                               float* __restrict__ OutF) {
    extern __shared__ float sm[];
    float* As = sm;              // [2][128*36]
    float* Bs = sm + 2 * 4608;   // [2][<=32*136 or 128*36]

    int tid = threadIdx.x;
    int warp = tid >> 5, lane = tid & 31;
    int g = lane >> 2, qq = lane & 3;
    int wm = warp >> 2, wn = warp & 3;
    int m0 = blockIdx.y * 128;
    int n0 = blockIdx.x * 128;

    int z = QKV ? (int)blockIdx.z : 3;
    const float* W = g_w4 + (size_t)z * (C_DIM * C_DIM);
    const float* X = QKV ? (z == 0 ? g_qn : g_vn) : g_aot;
    const float* bias = QKV ? (z == 0 ? b0 : (z == 1 ? b1 : b2)) : b0;
    float* Out = QKV ? (z == 0 ? g_qt : (z == 1 ? g_kt : g_v)) : OutF;
    int token_major = QKV && (z < 2);

    float acc[4][4][4];
    #pragma unroll
    for (int i = 0; i < 4; ++i)
        #pragma unroll
        for (int j = 0; j < 4; ++j)
            #pragma unroll
            for (int r = 0; r < 4; ++r) acc[i][j][r] = 0.f;

    // stage loader
    #define LOAD_STAGE(st, k0)                                                      \
    {                                                                               \
        _Pragma("unroll")                                                           \
        for (int i = 0; i < 4; ++i) {                                               \
            int c = tid + i * 256; int m = c >> 3, q = c & 7;                       \
            cp16(&As[(st) * 4608 + m * 36 + 4 * q],                                 \
                 &W[(size_t)(m0 + m) * 512 + (k0) + 4 * q]);                        \
        }                                                                           \
        if (BL == 0) {                                                              \
            _Pragma("unroll")                                                       \
            for (int i = 0; i < 4; ++i) {                                           \
                int c = tid + i * 256; int k = c >> 5, q = c & 31;                  \
                cp16(&Bs[(st) * 4608 + k * 136 + 4 * q],                            \
                     &X[(size_t)((k0) + k) * N_TOK + n0 + 4 * q]);                  \
            }                                                                       \
        } else {                                                                    \
            _Pragma("unroll")                                                       \
            for (int i = 0; i < 4; ++i) {                                           \
                int c = tid + i * 256; int n = c >> 3, q = c & 7;                   \
                cp16(&Bs[(st) * 4608 + n * 36 + 4 * q],                             \
                     &X[(size_t)(n0 + n) * 512 + (k0) + 4 * q]);                    \
            }                                                                       \
        }                                                                           \
    }

    LOAD_STAGE(0, 0); CP_COMMIT;

    #pragma unroll 1
    for (int kt = 0; kt < 16; ++kt) {
        int s = kt & 1;
        if (kt < 15) { LOAD_STAGE(s ^ 1, (kt + 1) * 32); CP_COMMIT; CP_WAIT1; }
        else         { CP_WAIT0; }
        __syncthreads();

        const unsigned* Au = (const unsigned*)(As + s * 4608);
        const unsigned* Bu = (const unsigned*)(Bs + s * 4608);
        #pragma unroll
        for (int kk = 0; kk < 4; ++kk) {
            unsigned a[4][4], b[4][2];
            #pragma unroll
            for (int mi = 0; mi < 4; ++mi) {
                int r = wm * 64 + mi * 16 + g;
                a[mi][0] = Au[r * 36 + kk * 8 + qq];
                a[mi][1] = Au[(r + 8) * 36 + kk * 8 + qq];
                a[mi][2] = Au[r * 36 + kk * 8 + qq + 4];
                a[mi][3] = Au[(r + 8) * 36 + kk * 8 + qq + 4];
            }
            #pragma unroll
            for (int ni = 0; ni < 4; ++ni) {
                int n = wn * 32 + ni * 8 + g;
                if (BL == 0) {
                    b[ni][0] = Bu[(kk * 8 + qq) * 136 + n];
                    b[ni][1] = Bu[(kk * 8 + qq + 4) * 136 + n];
                } else {
                    b[ni][0] = Bu[n * 36 + kk * 8 + qq];
                    b[ni][1] = Bu[n * 36 + kk * 8 + qq + 4];
                }
            }
            #pragma unroll
            for (int mi = 0; mi < 4; ++mi)
                #pragma unroll
                for (int ni = 0; ni < 4; ++ni)
                    mma_tf32(acc[mi][ni], a[mi], b[ni]);
        }
        __syncthreads();
    }
    #undef LOAD_STAGE

    const float IS2 = 0.70710678118654752f;
    #pragma unroll
    for (int mi = 0; mi < 4; ++mi) {
        int r = m0 + wm * 64 + mi * 16 + g;
        float bb0 = bias[r], bb8 = bias[r + 8];
        #pragma unroll
        for (int ni = 0; ni < 4; ++ni) {
            int n = n0 + wn * 32 + ni * 8 + 2 * qq;
            float c0 = acc[mi][ni][0] + bb0, c1 = acc[mi][ni][1] + bb0;
            float c2 = acc[mi][ni][2] + bb8, c3 = acc[mi][ni][3] + bb8;
            if (!QKV) {
                float2 r0 = *(const float2*)&resid[(size_t)r * N_TOK + n];
                float2 r8 = *(const float2*)&resid[(size_t)(r + 8) * N_TOK + n];
                c0 = (c0 + r0.x) * IS2; c1 = (c1 + r0.y) * IS2;
                c2 = (c2 + r8.x) * IS2; c3 = (c3 + r8.y) * IS2;
                *(float2*)&Out[(size_t)r * N_TOK + n] = make_float2(c0, c1);
                *(float2*)&Out[(size_t)(r + 8) * N_TOK + n] = make_float2(c2, c3);
            } else if (token_major) {
                Out[(size_t)n * 512 + r]           = rnd(c0);
                Out[(size_t)(n + 1) * 512 + r]     = rnd(c1);
                Out[(size_t)n * 512 + r + 8]       = rnd(c2);
                Out[(size_t)(n + 1) * 512 + r + 8] = rnd(c3);
            } else {
                *(float2*)&Out[(size_t)r * N_TOK + n] = make_float2(rnd(c0), rnd(c1));
                *(float2*)&Out[(size_t)(r + 8) * N_TOK + n] = make_float2(rnd(c2), rnd(c3));
            }
        }
    }
}

// ---------------------------------------------------------------------------
// Flash attention, tf32 MMA + cp.async double buffer.
// CTA = 256 queries x 1 head, 256 threads; warp owns 32 query rows.
// 64-key tiles. Q/K token-major, V channel-major, out token-major (rounded).
// ---------------------------------------------------------------------------
__global__ __launch_bounds__(256) void attn_tc() {
    extern __shared__ float sm[];
    float* Ks = sm;                  // [2][64*36]
    float* Vs = sm + 2 * 2304;       // [2][32*68]
    float* Ps = sm + 2 * 2304 + 2 * 2176;  // 8 warps x [32*68]

    int tid = threadIdx.x;
    int w = tid >> 5, lane = tid & 31;
    int g = lane >> 2, qq = lane & 3;
    int h = blockIdx.y;
    int q0 = blockIdx.x * 256 + w * 32;
    float* Pw = Ps + w * 2176;

    const float SCL = 0.25504448f;   // (1/sqrt(32)) * log2(e)

    unsigned qa[2][4][4];
    #pragma unroll
    for (int mi = 0; mi < 2; ++mi)
        #pragma unroll
        for (int kk = 0; kk < 4; ++kk) {
            const float* qp = &g_qt[(size_t)(q0 + mi * 16 + g) * 512 + h * HDIM + kk * 8 + qq];
            qa[mi][kk][0] = f2tf32(SCL * qp[0]);
            qa[mi][kk][1] = f2tf32(SCL * qp[8 * 512]);
            qa[mi][kk][2] = f2tf32(SCL * qp[4]);
            qa[mi][kk][3] = f2tf32(SCL * qp[8 * 512 + 4]);
        }

    float o[2][4][4];
    #pragma unroll
    for (int mi = 0; mi < 2; ++mi)
        #pragma unroll
        for (int nd = 0; nd < 4; ++nd)
            #pragma unroll
            for (int e = 0; e < 4; ++e) o[mi][nd][e] = 0.f;
    float m_[2][2] = {{-1e30f, -1e30f}, {-1e30f, -1e30f}};
    float l_[2][2] = {{0.f, 0.f}, {0.f, 0.f}};

    #define PREFETCH(st, kt0)                                                       \
    {                                                                               \
        _Pragma("unroll")                                                           \
        for (int i = 0; i < 2; ++i) {                                               \
            int c = tid + i * 256; int key = c >> 3, q = c & 7;                     \
            cp16(&Ks[(st) * 2304 + key * 36 + 4 * q],                               \
                 &g_kt[(size_t)((kt0) + key) * 512 + h * HDIM + 4 * q]);            \
        }                                                                           \
        _Pragma("unroll")                                                           \
        for (int i = 0; i < 2; ++i) {                                               \
            int c = tid + i * 256; int dd = c >> 4, q = c & 15;                     \
            cp16(&Vs[(st) * 2176 + dd * 68 + 4 * q],                                \
                 &g_v[(size_t)(h * HDIM + dd) * N_TOK + (kt0) + 4 * q]);            \
        }                                                                           \
    }

    PREFETCH(0, 0); CP_COMMIT;

    #pragma unroll 1
    for (int it = 0; it < 64; ++it) {
        int s = it & 1;
        if (it < 63) { PREFETCH(s ^ 1, (it + 1) * 64); CP_COMMIT; CP_WAIT1; }
        else         { CP_WAIT0; }
        __syncthreads();

        const unsigned* Ku = (const unsigned*)(Ks + s * 2304);
        // S = Q K^T  (32 x 64 per warp, logits already in log2 domain)
        float sc[2][8][4];
        #pragma unroll
        for (int nj = 0; nj < 8; ++nj) {
            sc[0][nj][0] = sc[0][nj][1] = sc[0][nj][2] = sc[0][nj][3] = 0.f;
            sc[1][nj][0] = sc[1][nj][1] = sc[1][nj][2] = sc[1][nj][3] = 0.f;
            #pragma unroll
            for (int kk = 0; kk < 4; ++kk) {
                unsigned bb[2];
                bb[0] = Ku[(nj * 8 + g) * 36 + kk * 8 + qq];
                bb[1] = Ku[(nj * 8 + g) * 36 + kk * 8 + qq + 4];
                mma_tf32(sc[0][nj], qa[0][kk], bb);
                mma_tf32(sc[1][nj], qa[1][kk], bb);
            }
        }

        // online softmax (exp2 domain)
        #pragma unroll
        for (int mi = 0; mi < 2; ++mi) {
            float mx0 = -1e30f, mx1 = -1e30f;
            #pragma unroll
            for (int nj = 0; nj < 8; ++nj) {
                mx0 = fmaxf(mx0, fmaxf(sc[mi][nj][0], sc[mi][nj][1]));
                mx1 = fmaxf(mx1, fmaxf(sc[mi][nj][2], sc[mi][nj][3]));
            }
            mx0 = fmaxf(mx0, __shfl_xor_sync(0xffffffffu, mx0, 1));
            mx0 = fmaxf(mx0, __shfl_xor_sync(0xffffffffu, mx0, 2));
            mx1 = fmaxf(mx1, __shfl_xor_sync(0xffffffffu, mx1, 1));
            mx1 = fmaxf(mx1, __shfl_xor_sync(0xffffffffu, mx1, 2));
            float nm0 = fmaxf(m_[mi][0], mx0), nm1 = fmaxf(m_[mi][1], mx1);
            float c0 = ex2(m_[mi][0] - nm0), c1 = ex2(m_[mi][1] - nm1);
            m_[mi][0] = nm0; m_[mi][1] = nm1;
            l_[mi][0] *= c0; l_[mi][1] *= c1;
            #pragma unroll
            for (int nd = 0; nd < 4; ++nd) {
                o[mi][nd][0] *= c0; o[mi][nd][1] *= c0;
                o[mi][nd][2] *= c1; o[mi][nd][3] *= c1;
            }
            int r0 = mi * 16 + g, r1 = r0 + 8;
            #pragma unroll
            for (int nj = 0; nj < 8; ++nj) {
                float e0 = ex2(sc[mi][nj][0] - nm0), e1 = ex2(sc[mi][nj][1] - nm0);
                float e2 = ex2(sc[mi][nj][2] - nm1), e3 = ex2(sc[mi][nj][3] - nm1);
                l_[mi][0] += e0 + e1; l_[mi][1] += e2 + e3;
                *(float2*)&Pw[r0 * 68 + nj * 8 + 2 * qq] = make_float2(rnd(e0), rnd(e1));
                *(float2*)&Pw[r1 * 68 + nj * 8 + 2 * qq] = make_float2(rnd(e2), rnd(e3));
            }
        }
        __syncwarp();

        // O += P V  (32 x 32 per warp, K = 64 keys)
        const unsigned* Vu = (const unsigned*)(Vs + s * 2176);
        const unsigned* Pu = (const unsigned*)Pw;
        #pragma unroll
        for (int kk = 0; kk < 8; ++kk) {
            unsigned bv[4][2];
            #pragma unroll
            for (int nd = 0; nd < 4; ++nd) {
                bv[nd][0] = Vu[(nd * 8 + g) * 68 + kk * 8 + qq];
                bv[nd][1] = Vu[(nd * 8 + g) * 68 + kk * 8 + qq + 4];
            }
            #pragma unroll
            for (int mi = 0; mi < 2; ++mi) {
                unsigned aa[4];
                aa[0] = Pu[(mi * 16 + g) * 68 + kk * 8 + qq];
                aa[1] = Pu[(mi * 16 + g + 8) * 68 + kk * 8 + qq];
                aa[2] = Pu[(mi * 16 + g) * 68 + kk * 8 + qq + 4];
                aa[3] = Pu[(mi * 16 + g + 8) * 68 + kk * 8 + qq + 4];
                #pragma unroll
                for (int nd = 0; nd < 4; ++nd)
                    mma_tf32(o[mi][nd], aa, bv[nd]);
            }
        }
        __syncthreads();
    }
    #undef PREFETCH

    #pragma unroll
    for (int mi = 0; mi < 2; ++mi) {
        l_[mi][0] += __shfl_xor_sync(0xffffffffu, l_[mi][0], 1);
        l_[mi][0] += __shfl_xor_sync(0xffffffffu, l_[mi][0], 2);
        l_[mi][1] += __shfl_xor_sync(0xffffffffu, l_[mi][1], 1);
        l_[mi][1] += __shfl_xor_sync(0xffffffffu, l_[mi][1], 2);
        float ia = 1.f / l_[mi][0], ib = 1.f / l_[mi][1];
        #pragma unroll
        for (int nd = 0; nd < 4; ++nd) {
            int d = h * HDIM + nd * 8 + 2 * qq;
            *(float2*)&g_aot[(size_t)(q0 + mi * 16 + g) * 512 + d] =
                make_float2(rnd(o[mi][nd][0] * ia), rnd(o[mi][nd][1] * ia));
            *(float2*)&g_aot[(size_t)(q0 + mi * 16 + g + 8) * 512 + d] =
                make_float2(rnd(o[mi][nd][2] * ib), rnd(o[mi][nd][3] * ib));
        }
    }
}

// ---------------------------------------------------------------------------
// Launch
// ---------------------------------------------------------------------------
extern "C" void kernel_launch(void* const* d_in, const int* in_sizes, int n_in,
                              void* d_out, int out_size) {
    const float* x   = (const float*)d_in[0];
    const float* gnw = (const float*)d_in[1];
    const float* gnb = (const float*)d_in[2];
    const float* wq  = (const float*)d_in[3];
    const float* bq  = (const float*)d_in[4];
    const float* wk  = (const float*)d_in[5];
    const float* bk  = (const float*)d_in[6];
    const float* wv  = (const float*)d_in[7];
    const float* bv  = (const float*)d_in[8];
    const float* wo  = (const float*)d_in[9];
    const float* bo  = (const float*)d_in[10];
    float* out = (float*)d_out;

    const int GEMM_SMEM = 4 * 4608 * 4;                    // 73728 B
    const int ATTN_SMEM = (2 * 2304 + 2 * 2176 + 8 * 2176) * 4;  // 105472 B
    cudaFuncSetAttribute(gemm_tc<0, 1>, cudaFuncAttributeMaxDynamicSharedMemorySize, GEMM_SMEM);
    cudaFuncSetAttribute(gemm_tc<1, 0>, cudaFuncAttributeMaxDynamicSharedMemorySize, GEMM_SMEM);
    cudaFuncSetAttribute(attn_tc,       cudaFuncAttributeMaxDynamicSharedMemorySize, ATTN_SMEM);

    chan_stats<<<C_DIM, 256>>>(x);
    gn_finalize<<<1, 32>>>(gnw, gnb);
    apply_both<<<512, 256>>>(x);
    round_w<<<256, 256>>>(wq, wk, wv, wo);

    dim3 gqkv(N_TOK / 128, C_DIM / 128, 3);   // (32, 4, 3)
    gemm_tc<0, 1><<<gqkv, 256, GEMM_SMEM>>>(bq, bk, bv, nullptr, nullptr);

    dim3 ag(N_TOK / 256, HEADS);              // (16, 16)
    attn_tc<<<ag, 256, ATTN_SMEM>>>();

    dim3 go(N_TOK / 128, C_DIM / 128, 1);     // (32, 4)
    gemm_tc<1, 0><<<go, 256, GEMM_SMEM>>>(bo, nullptr, nullptr, x, out);
}

// round 5
// speedup vs baseline: 6.2140x; 1.5438x over previous
#include <cuda_runtime.h>
#include <cuda_fp16.h>

#define C_DIM 512
#define N_TOK 4096
#define HEADS 16
#define HDIM  32
// (1/sqrt(32)) * log2(e), folded into wq/bq
#define ALPHA 0.25504448f

// ---------------- scratch ----------------
__device__ __half g_qnt[N_TOK * C_DIM];     // GN1(x), token-major fp16
__device__ __half g_vnt[N_TOK * C_DIM];     // GN2,    token-major fp16
__device__ __half g_qt [N_TOK * C_DIM];     // Q (pre-scaled), token-major fp16
__device__ __half g_kt [N_TOK * C_DIM];     // K, token-major fp16
__device__ __half g_vt [N_TOK * C_DIM];     // V, token-major fp16
__device__ __half g_aot[N_TOK * C_DIM];     // attn out, token-major fp16
__device__ __half g_wh [4 * C_DIM * C_DIM]; // fp16 weights [z][m][k] (wq scaled)
__device__ float g_cs[C_DIM], g_cq[C_DIM];
__device__ float g_a1[C_DIM], g_c1[C_DIM];
__device__ float g_av[C_DIM], g_cv[C_DIM];

// ---------------- helpers ----------------
__device__ __forceinline__ float ex2(float x) {
    float r; asm("ex2.approx.ftz.f32 %0, %1;" : "=f"(r) : "f"(x)); return r;
}
__device__ __forceinline__ unsigned packh2(float lo, float hi) {
    unsigned u; asm("cvt.rn.f16x2.f32 %0, %1, %2;" : "=r"(u) : "f"(hi), "f"(lo)); return u;
}
__device__ __forceinline__ void mma16816(float* d, const unsigned* a, unsigned b0, unsigned b1) {
    asm volatile(
        "mma.sync.aligned.m16n8k16.row.col.f32.f16.f16.f32 "
        "{%0,%1,%2,%3}, {%4,%5,%6,%7}, {%8,%9}, {%0,%1,%2,%3};"
        : "+f"(d[0]), "+f"(d[1]), "+f"(d[2]), "+f"(d[3])
        : "r"(a[0]), "r"(a[1]), "r"(a[2]), "r"(a[3]), "r"(b0), "r"(b1));
}
__device__ __forceinline__ void ldsm4t(unsigned* r, const void* p) {
    unsigned a = (unsigned)__cvta_generic_to_shared(p);
    asm volatile("ldmatrix.sync.aligned.m8n8.x4.trans.shared.b16 {%0,%1,%2,%3}, [%4];"
                 : "=r"(r[0]), "=r"(r[1]), "=r"(r[2]), "=r"(r[3]) : "r"(a));
}
__device__ __forceinline__ void cp16(void* smem, const void* gmem) {
    unsigned sa = (unsigned)__cvta_generic_to_shared(smem);
    asm volatile("cp.async.cg.shared.global [%0], [%1], 16;" :: "r"(sa), "l"(gmem) : "memory");
}
#define CP_COMMIT asm volatile("cp.async.commit_group;" ::: "memory")
#define CP_WAIT1  asm volatile("cp.async.wait_group 1;" ::: "memory")
#define CP_WAIT0  asm volatile("cp.async.wait_group 0;" ::: "memory")

// ---------------- GroupNorm stats ----------------
__device__ __forceinline__ void blk_reduce2(float& s, float& sq, float* sh) {
    #pragma unroll
    for (int off = 16; off > 0; off >>= 1) {
        s  += __shfl_down_sync(0xffffffffu, s,  off);
        sq += __shfl_down_sync(0xffffffffu, sq, off);
    }
    int w = threadIdx.x >> 5, lane = threadIdx.x & 31;
    if (lane == 0) { sh[w] = s; sh[8 + w] = sq; }
    __syncthreads();
    if (threadIdx.x == 0) {
        float ts = 0.f, tq = 0.f;
        #pragma unroll
        for (int i = 0; i < 8; ++i) { ts += sh[i]; tq += sh[8 + i]; }
        s = ts; sq = tq;
    }
}

__global__ __launch_bounds__(256) void chan_stats(const float* __restrict__ x) {
    __shared__ float sh[16];
    int c = blockIdx.x;
    const float4* p = (const float4*)(x + (size_t)c * N_TOK);
    float s = 0.f, sq = 0.f;
    #pragma unroll
    for (int i = threadIdx.x; i < N_TOK / 4; i += 256) {
        float4 v = p[i];
        s  += (v.x + v.y) + (v.z + v.w);
        sq += v.x * v.x + v.y * v.y + v.z * v.z + v.w * v.w;
    }
    blk_reduce2(s, sq, sh);
    if (threadIdx.x == 0) { g_cs[c] = s; g_cq[c] = sq; }
}

__global__ void gn_finalize(const float* __restrict__ w, const float* __restrict__ b) {
    int g = threadIdx.x;
    if (g >= 32) return;
    const float inv = 1.f / (float)N_TOK;
    float m1 = 0.f, E1 = 0.f;
    #pragma unroll
    for (int c = 0; c < 16; ++c) {
        int ch = g * 16 + c;
        m1 += g_cs[ch] * inv;
        E1 += g_cq[ch] * inv;
    }
    m1 *= (1.f / 16.f); E1 *= (1.f / 16.f);
    float is1 = rsqrtf(E1 - m1 * m1 + 1e-6f);
    float m2 = 0.f, E2 = 0.f;
    #pragma unroll
    for (int c = 0; c < 16; ++c) {
        int ch = g * 16 + c;
        float mc = g_cs[ch] * inv, Ec = g_cq[ch] * inv;
        float a1 = w[ch] * is1;
        float c1 = b[ch] - m1 * a1;
        g_a1[ch] = a1; g_c1[ch] = c1;
        m2 += a1 * mc + c1;
        E2 += a1 * a1 * Ec + 2.f * a1 * c1 * mc + c1 * c1;
    }
    m2 *= (1.f / 16.f); E2 *= (1.f / 16.f);
    float is2 = rsqrtf(E2 - m2 * m2 + 1e-6f);
    #pragma unroll
    for (int c = 0; c < 16; ++c) {
        int ch = g * 16 + c;
        float a2 = w[ch] * is2;
        float c2 = b[ch] - m2 * a2;
        g_av[ch] = a2 * g_a1[ch];
        g_cv[ch] = a2 * g_c1[ch] + c2;
    }
}

// apply GN affines with transpose: x[c][n] -> qnt/vnt token-major fp16
__global__ __launch_bounds__(256) void apply_tr(const float* __restrict__ x) {
    __shared__ __half sq[64][132];
    __shared__ __half sv[64][132];
    int n0 = blockIdx.x * 64;
    int tid = threadIdx.x;
    for (int cc = 0; cc < 4; ++cc) {
        #pragma unroll
        for (int i = 0; i < 32; ++i) {
            int idx = tid + i * 256;
            int t = idx & 63, ci = idx >> 6;
            int c = cc * 128 + ci;
            float v = x[(size_t)c * N_TOK + n0 + t];
            sq[t][ci] = __float2half_rn(v * g_a1[c] + g_c1[c]);
            sv[t][ci] = __float2half_rn(v * g_av[c] + g_cv[c]);
        }
        __syncthreads();
        #pragma unroll
        for (int i = 0; i < 16; ++i) {
            int idx = tid + i * 256;
            int t = idx >> 6, j = idx & 63;
            __half2 q2 = __halves2half2(sq[t][2 * j], sq[t][2 * j + 1]);
            __half2 v2 = __halves2half2(sv[t][2 * j], sv[t][2 * j + 1]);
            *(__half2*)&g_qnt[(size_t)(n0 + t) * 512 + cc * 128 + 2 * j] = q2;
            *(__half2*)&g_vnt[(size_t)(n0 + t) * 512 + cc * 128 + 2 * j] = v2;
        }
        __syncthreads();
    }
}

// weights -> fp16 (wq scaled by ALPHA)
__global__ __launch_bounds__(256) void round_wh(const float* __restrict__ wq,
                                                const float* __restrict__ wk,
                                                const float* __restrict__ wv,
                                                const float* __restrict__ wo) {
    int total = 4 * C_DIM * C_DIM / 4;
    for (int i = blockIdx.x * 256 + threadIdx.x; i < total; i += gridDim.x * 256) {
        int sel = i >> 16, loc = i & 65535;
        const float4* src = (const float4*)(sel == 0 ? wq : sel == 1 ? wk : sel == 2 ? wv : wo);
        float sc = (sel == 0) ? ALPHA : 1.f;
        float4 v = src[loc];
        uint2 o;
        o.x = packh2(v.x * sc, v.y * sc);
        o.y = packh2(v.z * sc, v.w * sc);
        *(uint2*)&g_wh[(size_t)i * 4] = o;
    }
}

// ---------------------------------------------------------------------------
// fp16 GEMM: C[token][outch] = Xt[token][512] * W[outch][512]^T + bias.
// FIN=0: z=blockIdx.z in {Q,K,V}; fp16 token-major output (bq scaled for Q).
// FIN=1: wo * aot; fp32 channel-major output + residual, * 1/sqrt(2).
// Block 128(tok) x 128(ch), BK=32, 256 threads, warp tile 64x32, m16n8k16.
// ---------------------------------------------------------------------------
template<int FIN>
__global__ __launch_bounds__(256, 2) void gemm_h(const float* __restrict__ b0p,
                                                 const float* __restrict__ b1p,
                                                 const float* __restrict__ b2p,
                                                 const float* __restrict__ resid,
                                                 float* __restrict__ OutF) {
    __shared__ __half As[2][128 * 40];
    __shared__ __half Bs[2][128 * 40];

    int tid = threadIdx.x;
    int warp = tid >> 5, lane = tid & 31;
    int g = lane >> 2, qq = lane & 3;
    int wm = warp >> 2, wn = warp & 3;
    int m0 = blockIdx.x * 128;       // tokens
    int n0 = blockIdx.y * 128;       // out channels

    int z = FIN ? 3 : (int)blockIdx.z;
    const __half* W  = g_wh + (size_t)z * (C_DIM * C_DIM);
    const __half* Xt = FIN ? g_aot : (z == 0 ? g_qnt : g_vnt);
    const float* bias = FIN ? b0p : (z == 0 ? b0p : (z == 1 ? b1p : b2p));
    __half* OutH = z == 0 ? g_qt : (z == 1 ? g_kt : g_vt);

    float acc[4][4][4];
    #pragma unroll
    for (int i = 0; i < 4; ++i)
        #pragma unroll
        for (int j = 0; j < 4; ++j)
            #pragma unroll
            for (int r = 0; r < 4; ++r) acc[i][j][r] = 0.f;

    #define GLOAD(st, k0)                                                       \
    {                                                                           \
        _Pragma("unroll")                                                       \
        for (int i = 0; i < 2; ++i) {                                           \
            int idx = tid + i * 256; int m = idx >> 2, q = idx & 3;             \
            cp16(&As[st][m * 40 + q * 8], &Xt[(size_t)(m0 + m) * 512 + (k0) + q * 8]); \
        }                                                                       \
        _Pragma("unroll")                                                       \
        for (int i = 0; i < 2; ++i) {                                           \
            int idx = tid + i * 256; int n = idx >> 2, q = idx & 3;             \
            cp16(&Bs[st][n * 40 + q * 8], &W[(size_t)(n0 + n) * 512 + (k0) + q * 8]);  \
        }                                                                       \
    }

    GLOAD(0, 0); CP_COMMIT;

    #pragma unroll 1
    for (int kt = 0; kt < 16; ++kt) {
        int s = kt & 1;
        if (kt < 15) { GLOAD(s ^ 1, (kt + 1) * 32); CP_COMMIT; CP_WAIT1; }
        else         { CP_WAIT0; }
        __syncthreads();

        const unsigned* Au = (const unsigned*)As[s];
        const unsigned* Bu = (const unsigned*)Bs[s];
        #pragma unroll
        for (int kk = 0; kk < 2; ++kk) {
            unsigned a[4][4], b[4][2];
            #pragma unroll
            for (int mi = 0; mi < 4; ++mi) {
                int r = wm * 64 + mi * 16 + g;
                a[mi][0] = Au[r * 20 + kk * 8 + qq];
                a[mi][1] = Au[(r + 8) * 20 + kk * 8 + qq];
                a[mi][2] = Au[r * 20 + kk * 8 + qq + 4];
                a[mi][3] = Au[(r + 8) * 20 + kk * 8 + qq + 4];
            }
            #pragma unroll
            for (int ni = 0; ni < 4; ++ni) {
                int n = wn * 32 + ni * 8 + g;
                b[ni][0] = Bu[n * 20 + kk * 8 + qq];
                b[ni][1] = Bu[n * 20 + kk * 8 + qq + 4];
            }
            #pragma unroll
            for (int mi = 0; mi < 4; ++mi)
                #pragma unroll
                for (int ni = 0; ni < 4; ++ni)
                    mma16816(acc[mi][ni], a[mi], b[ni][0], b[ni][1]);
        }
        __syncthreads();
    }
    #undef GLOAD

    const float IS2 = 0.70710678118654752f;
    float bscale = (!FIN && z == 0) ? ALPHA : 1.f;
    #pragma unroll
    for (int mi = 0; mi < 4; ++mi) {
        int t = m0 + wm * 64 + mi * 16 + g;          // token (row g); +8 for c2/c3
        #pragma unroll
        for (int ni = 0; ni < 4; ++ni) {
            int ch = n0 + wn * 32 + ni * 8 + 2 * qq;
            float bb0 = bias[ch] * bscale, bb1 = bias[ch + 1] * bscale;
            float c0 = acc[mi][ni][0] + bb0, c1 = acc[mi][ni][1] + bb1;
            float c2 = acc[mi][ni][2] + bb0, c3 = acc[mi][ni][3] + bb1;
            if (FIN) {
                size_t i00 = (size_t)ch * N_TOK + t;
                size_t i10 = (size_t)(ch + 1) * N_TOK + t;
                OutF[i00]     = (c0 + resid[i00])     * IS2;
                OutF[i10]     = (c1 + resid[i10])     * IS2;
                OutF[i00 + 8] = (c2 + resid[i00 + 8]) * IS2;
                OutF[i10 + 8] = (c3 + resid[i10 + 8]) * IS2;
            } else {
                *(unsigned*)&OutH[(size_t)t * 512 + ch]       = packh2(c0, c1);
                *(unsigned*)&OutH[(size_t)(t + 8) * 512 + ch] = packh2(c2, c3);
            }
        }
    }
}

// ---------------------------------------------------------------------------
// Flash attention fp16: CTA = 128 queries x head, 8 warps x 16 q-rows.
// 64-key tiles, cp.async double-buffered; P stays in registers (FA2 layout).
// Q pre-scaled by (1/sqrt(32))*log2e -> exp2 softmax.
// ---------------------------------------------------------------------------
__global__ __launch_bounds__(256, 2) void attn_h() {
    __shared__ __half Ks[2][64 * 40];
    __shared__ __half Vs[2][64 * 40];

    int tid = threadIdx.x;
    int w = tid >> 5, lane = tid & 31;
    int g = lane >> 2, qq = lane & 3;
    int h = blockIdx.y;
    int hb = h * HDIM;
    int q0 = blockIdx.x * 128 + w * 16;

    // Q fragments from gmem (token-major, already scaled)
    unsigned qa[2][4];
    #pragma unroll
    for (int kk = 0; kk < 2; ++kk) {
        const __half* qp = &g_qt[(size_t)(q0 + g) * 512 + hb + kk * 16 + 2 * qq];
        qa[kk][0] = *(const unsigned*)qp;
        qa[kk][1] = *(const unsigned*)(qp + 8 * 512);
        qa[kk][2] = *(const unsigned*)(qp + 8);
        qa[kk][3] = *(const unsigned*)(qp + 8 * 512 + 8);
    }

    float o[4][4];
    #pragma unroll
    for (int nd = 0; nd < 4; ++nd)
        #pragma unroll
        for (int e = 0; e < 4; ++e) o[nd][e] = 0.f;
    float m0 = -1e30f, m1 = -1e30f, l0 = 0.f, l1 = 0.f;

    // per-tile loads: 64 rows x 32 halves each for K and V -> 1 cp16/thread each
    int lrow = tid >> 2, lq = tid & 3;

    #define APRE(st, kt0)                                                        \
    {                                                                            \
        cp16(&Ks[st][lrow * 40 + lq * 8],                                        \
             &g_kt[(size_t)((kt0) + lrow) * 512 + hb + lq * 8]);                 \
        cp16(&Vs[st][lrow * 40 + lq * 8],                                        \
             &g_vt[(size_t)((kt0) + lrow) * 512 + hb + lq * 8]);                 \
    }

    APRE(0, 0); CP_COMMIT;

    #pragma unroll 1
    for (int it = 0; it < 64; ++it) {
        int s = it & 1;
        if (it < 63) { APRE(s ^ 1, (it + 1) * 64); CP_COMMIT; CP_WAIT1; }
        else         { CP_WAIT0; }
        __syncthreads();

        // S = Q K^T (16q x 64k), fp32 accum
        const unsigned* Ku = (const unsigned*)Ks[s];
        float sc[8][4];
        #pragma unroll
        for (int nj = 0; nj < 8; ++nj) {
            sc[nj][0] = sc[nj][1] = sc[nj][2] = sc[nj][3] = 0.f;
            int krow = (nj * 8 + g) * 20;
            #pragma unroll
            for (int kk = 0; kk < 2; ++kk)
                mma16816(sc[nj], qa[kk], Ku[krow + kk * 8 + qq], Ku[krow + kk * 8 + qq + 4]);
        }

        // online softmax (log2 domain)
        float mx0 = -1e30f, mx1 = -1e30f;
        #pragma unroll
        for (int nj = 0; nj < 8; ++nj) {
            mx0 = fmaxf(mx0, fmaxf(sc[nj][0], sc[nj][1]));
            mx1 = fmaxf(mx1, fmaxf(sc[nj][2], sc[nj][3]));
        }
        mx0 = fmaxf(mx0, __shfl_xor_sync(0xffffffffu, mx0, 1));
        mx0 = fmaxf(mx0, __shfl_xor_sync(0xffffffffu, mx0, 2));
        mx1 = fmaxf(mx1, __shfl_xor_sync(0xffffffffu, mx1, 1));
        mx1 = fmaxf(mx1, __shfl_xor_sync(0xffffffffu, mx1, 2));
        float nm0 = fmaxf(m0, mx0), nm1 = fmaxf(m1, mx1);
        float cr0 = ex2(m0 - nm0), cr1 = ex2(m1 - nm1);
        m0 = nm0; m1 = nm1;
        l0 *= cr0; l1 *= cr1;
        #pragma unroll
        for (int nd = 0; nd < 4; ++nd) {
            o[nd][0] *= cr0; o[nd][1] *= cr0;
            o[nd][2] *= cr1; o[nd][3] *= cr1;
        }

        // exp + pack P into A-fragments (no smem round-trip)
        unsigned ph[4][4];
        #pragma unroll
        for (int kk = 0; kk < 4; ++kk) {
            float e0 = ex2(sc[2*kk][0] - nm0), e1 = ex2(sc[2*kk][1] - nm0);
            float e2 = ex2(sc[2*kk][2] - nm1), e3 = ex2(sc[2*kk][3] - nm1);
            float f0 = ex2(sc[2*kk+1][0] - nm0), f1 = ex2(sc[2*kk+1][1] - nm0);
            float f2 = ex2(sc[2*kk+1][2] - nm1), f3 = ex2(sc[2*kk+1][3] - nm1);
            l0 += (e0 + e1) + (f0 + f1);
            l1 += (e2 + e3) + (f2 + f3);
            ph[kk][0] = packh2(e0, e1);
            ph[kk][1] = packh2(e2, e3);
            ph[kk][2] = packh2(f0, f1);
            ph[kk][3] = packh2(f2, f3);
        }

        // O += P V : V fragments via ldmatrix.x4.trans from [key][d] tile
        int vr = (lane & 15) * 40 + ((lane >> 4) << 3);
        #pragma unroll
        for (int kk = 0; kk < 4; ++kk) {
            unsigned v0[4], v1[4];
            ldsm4t(v0, &Vs[s][kk * 16 * 40 + vr]);        // d 0..15
            ldsm4t(v1, &Vs[s][kk * 16 * 40 + vr + 16]);   // d 16..31
            mma16816(o[0], ph[kk], v0[0], v0[1]);
            mma16816(o[1], ph[kk], v0[2], v0[3]);
            mma16816(o[2], ph[kk], v1[0], v1[1]);
            mma16816(o[3], ph[kk], v1[2], v1[3]);
        }
        __syncthreads();
    }
    #undef APRE

    l0 += __shfl_xor_sync(0xffffffffu, l0, 1);
    l0 += __shfl_xor_sync(0xffffffffu, l0, 2);
    l1 += __shfl_xor_sync(0xffffffffu, l1, 1);
    l1 += __shfl_xor_sync(0xffffffffu, l1, 2);
    float i0 = 1.f / l0, i1 = 1.f / l1;

    #pragma unroll
    for (int nd = 0; nd < 4; ++nd) {
        int d = hb + nd * 8 + 2 * qq;
        *(unsigned*)&g_aot[(size_t)(q0 + g) * 512 + d]     = packh2(o[nd][0] * i0, o[nd][1] * i0);
        *(unsigned*)&g_aot[(size_t)(q0 + g + 8) * 512 + d] = packh2(o[nd][2] * i1, o[nd][3] * i1);
    }
}

// ---------------------------------------------------------------------------
// Launch
// ---------------------------------------------------------------------------
extern "C" void kernel_launch(void* const* d_in, const int* in_sizes, int n_in,
                              void* d_out, int out_size) {
    const float* x   = (const float*)d_in[0];
    const float* gnw = (const float*)d_in[1];
    const float* gnb = (const float*)d_in[2];
    const float* wq  = (const float*)d_in[3];
    const float* bq  = (const float*)d_in[4];
    const float* wk  = (const float*)d_in[5];
    const float* bk  = (const float*)d_in[6];
    const float* wv  = (const float*)d_in[7];
    const float* bv  = (const float*)d_in[8];
    const float* wo  = (const float*)d_in[9];
    const float* bo  = (const float*)d_in[10];
    float* out = (float*)d_out;

    chan_stats<<<C_DIM, 256>>>(x);
    gn_finalize<<<1, 32>>>(gnw, gnb);
    apply_tr<<<N_TOK / 64, 256>>>(x);
    round_wh<<<256, 256>>>(wq, wk, wv, wo);

    dim3 gqkv(N_TOK / 128, C_DIM / 128, 3);     // (32, 4, 3)
    gemm_h<0><<<gqkv, 256>>>(bq, bk, bv, nullptr, nullptr);

    dim3 ag(N_TOK / 128, HEADS);                // (32, 16)
    attn_h<<<ag, 256>>>();

    dim3 go(N_TOK / 128, C_DIM / 128, 1);
    gemm_h<1><<<go, 256>>>(bo, nullptr, nullptr, x, out);
}

// round 6
// speedup vs baseline: 6.8670x; 1.1051x over previous
#include <cuda_runtime.h>
#include <cuda_fp16.h>

#define C_DIM 512
#define N_TOK 4096
#define HEADS 16
#define HDIM  32
// (1/sqrt(32)) * log2(e), folded into wq/bq
#define ALPHA 0.25504448f
#define ONESH2 0x3C003C00u

// ---------------- scratch ----------------
__device__ __half g_qnt[N_TOK * C_DIM];
__device__ __half g_vnt[N_TOK * C_DIM];
__device__ __half g_qt [N_TOK * C_DIM];
__device__ __half g_kt [N_TOK * C_DIM];
__device__ __half g_vt [N_TOK * C_DIM];
__device__ __half g_aot[N_TOK * C_DIM];
__device__ __half g_wh [4 * C_DIM * C_DIM];
__device__ float g_cs[C_DIM], g_cq[C_DIM];
__device__ float g_a1[C_DIM], g_c1[C_DIM];
__device__ float g_av[C_DIM], g_cv[C_DIM];

// ---------------- helpers ----------------
__device__ __forceinline__ float ex2(float x) {
    float r; asm("ex2.approx.ftz.f32 %0, %1;" : "=f"(r) : "f"(x)); return r;
}
__device__ __forceinline__ unsigned h2ex2(unsigned x) {
    unsigned r; asm("ex2.approx.f16x2 %0, %1;" : "=r"(r) : "r"(x)); return r;
}
__device__ __forceinline__ unsigned packh2(float lo, float hi) {
    unsigned u; asm("cvt.rn.f16x2.f32 %0, %1, %2;" : "=r"(u) : "f"(hi), "f"(lo)); return u;
}
__device__ __forceinline__ void mma16816(float* d, const unsigned* a, unsigned b0, unsigned b1) {
    asm volatile(
        "mma.sync.aligned.m16n8k16.row.col.f32.f16.f16.f32 "
        "{%0,%1,%2,%3}, {%4,%5,%6,%7}, {%8,%9}, {%0,%1,%2,%3};"
        : "+f"(d[0]), "+f"(d[1]), "+f"(d[2]), "+f"(d[3])
        : "r"(a[0]), "r"(a[1]), "r"(a[2]), "r"(a[3]), "r"(b0), "r"(b1));
}
__device__ __forceinline__ void ldsm4t(unsigned* r, const void* p) {
    unsigned a = (unsigned)__cvta_generic_to_shared(p);
    asm volatile("ldmatrix.sync.aligned.m8n8.x4.trans.shared.b16 {%0,%1,%2,%3}, [%4];"
                 : "=r"(r[0]), "=r"(r[1]), "=r"(r[2]), "=r"(r[3]) : "r"(a));
}
__device__ __forceinline__ void cp16(void* smem, const void* gmem) {
    unsigned sa = (unsigned)__cvta_generic_to_shared(smem);
    asm volatile("cp.async.cg.shared.global [%0], [%1], 16;" :: "r"(sa), "l"(gmem) : "memory");
}
#define CP_COMMIT asm volatile("cp.async.commit_group;" ::: "memory")
#define CP_WAIT1  asm volatile("cp.async.wait_group 1;" ::: "memory")
#define CP_WAIT0  asm volatile("cp.async.wait_group 0;" ::: "memory")

// ---------------- GroupNorm stats ----------------
__device__ __forceinline__ void blk_reduce2(float& s, float& sq, float* sh) {
    #pragma unroll
    for (int off = 16; off > 0; off >>= 1) {
        s  += __shfl_down_sync(0xffffffffu, s,  off);
        sq += __shfl_down_sync(0xffffffffu, sq, off);
    }
    int w = threadIdx.x >> 5, lane = threadIdx.x & 31;
    if (lane == 0) { sh[w] = s; sh[8 + w] = sq; }
    __syncthreads();
    if (threadIdx.x == 0) {
        float ts = 0.f, tq = 0.f;
        #pragma unroll
        for (int i = 0; i < 8; ++i) { ts += sh[i]; tq += sh[8 + i]; }
        s = ts; sq = tq;
    }
}

__global__ __launch_bounds__(256) void chan_stats(const float* __restrict__ x) {
    __shared__ float sh[16];
    int c = blockIdx.x;
    const float4* p = (const float4*)(x + (size_t)c * N_TOK);
    float s = 0.f, sq = 0.f;
    #pragma unroll
    for (int i = threadIdx.x; i < N_TOK / 4; i += 256) {
        float4 v = p[i];
        s  += (v.x + v.y) + (v.z + v.w);
        sq += v.x * v.x + v.y * v.y + v.z * v.z + v.w * v.w;
    }
    blk_reduce2(s, sq, sh);
    if (threadIdx.x == 0) { g_cs[c] = s; g_cq[c] = sq; }
}

__global__ void gn_finalize(const float* __restrict__ w, const float* __restrict__ b) {
    int g = threadIdx.x;
    if (g >= 32) return;
    const float inv = 1.f / (float)N_TOK;
    float m1 = 0.f, E1 = 0.f;
    #pragma unroll
    for (int c = 0; c < 16; ++c) {
        int ch = g * 16 + c;
        m1 += g_cs[ch] * inv;
        E1 += g_cq[ch] * inv;
    }
    m1 *= (1.f / 16.f); E1 *= (1.f / 16.f);
    float is1 = rsqrtf(E1 - m1 * m1 + 1e-6f);
    float m2 = 0.f, E2 = 0.f;
    #pragma unroll
    for (int c = 0; c < 16; ++c) {
        int ch = g * 16 + c;
        float mc = g_cs[ch] * inv, Ec = g_cq[ch] * inv;
        float a1 = w[ch] * is1;
        float c1 = b[ch] - m1 * a1;
        g_a1[ch] = a1; g_c1[ch] = c1;
        m2 += a1 * mc + c1;
        E2 += a1 * a1 * Ec + 2.f * a1 * c1 * mc + c1 * c1;
    }
    m2 *= (1.f / 16.f); E2 *= (1.f / 16.f);
    float is2 = rsqrtf(E2 - m2 * m2 + 1e-6f);
    #pragma unroll
    for (int c = 0; c < 16; ++c) {
        int ch = g * 16 + c;
        float a2 = w[ch] * is2;
        float c2 = b[ch] - m2 * a2;
        g_av[ch] = a2 * g_a1[ch];
        g_cv[ch] = a2 * g_c1[ch] + c2;
    }
}

// GN apply with transpose: x[c][n] -> qnt/vnt token-major fp16.
// grid (N_TOK/64, 4): blockIdx.y selects 128-channel slab.
__global__ __launch_bounds__(256) void apply_tr(const float* __restrict__ x) {
    __shared__ __half sq[64][132];
    __shared__ __half sv[64][132];
    int n0 = blockIdx.x * 64;
    int cc = blockIdx.y;
    int tid = threadIdx.x;
    #pragma unroll
    for (int i = 0; i < 32; ++i) {
        int idx = tid + i * 256;
        int t = idx & 63, ci = idx >> 6;
        int c = cc * 128 + ci;
        float v = x[(size_t)c * N_TOK + n0 + t];
        sq[t][ci] = __float2half_rn(v * g_a1[c] + g_c1[c]);
        sv[t][ci] = __float2half_rn(v * g_av[c] + g_cv[c]);
    }
    __syncthreads();
    #pragma unroll
    for (int i = 0; i < 16; ++i) {
        int idx = tid + i * 256;
        int t = idx >> 6, j = idx & 63;
        __half2 q2 = __halves2half2(sq[t][2 * j], sq[t][2 * j + 1]);
        __half2 v2 = __halves2half2(sv[t][2 * j], sv[t][2 * j + 1]);
        *(__half2*)&g_qnt[(size_t)(n0 + t) * 512 + cc * 128 + 2 * j] = q2;
        *(__half2*)&g_vnt[(size_t)(n0 + t) * 512 + cc * 128 + 2 * j] = v2;
    }
}

// weights -> fp16 (wq scaled by ALPHA)
__global__ __launch_bounds__(256) void round_wh(const float* __restrict__ wq,
                                                const float* __restrict__ wk,
                                                const float* __restrict__ wv,
                                                const float* __restrict__ wo) {
    int total = 4 * C_DIM * C_DIM / 4;
    for (int i = blockIdx.x * 256 + threadIdx.x; i < total; i += gridDim.x * 256) {
        int sel = i >> 16, loc = i & 65535;
        const float4* src = (const float4*)(sel == 0 ? wq : sel == 1 ? wk : sel == 2 ? wv : wo);
        float sc = (sel == 0) ? ALPHA : 1.f;
        float4 v = src[loc];
        uint2 o;
        o.x = packh2(v.x * sc, v.y * sc);
        o.y = packh2(v.z * sc, v.w * sc);
        *(uint2*)&g_wh[(size_t)i * 4] = o;
    }
}

// ---------------------------------------------------------------------------
// fp16 GEMM: C[token][outch] = Xt[token][512] * W[outch][512]^T + bias.
// Block 64(tok) x 128(ch), BK=32, 256 threads, warp tile 32x32.
// FIN=0: z in {Q,K,V}, fp16 token-major out. FIN=1: fp32 ch-major + residual.
// ---------------------------------------------------------------------------
template<int FIN>
__global__ __launch_bounds__(256, 2) void gemm_h(const float* __restrict__ b0p,
                                                 const float* __restrict__ b1p,
                                                 const float* __restrict__ b2p,
                                                 const float* __restrict__ resid,
                                                 float* __restrict__ OutF) {
    __shared__ __half As[2][64 * 40];
    __shared__ __half Bs[2][128 * 40];

    int tid = threadIdx.x;
    int warp = tid >> 5, lane = tid & 31;
    int g = lane >> 2, qq = lane & 3;
    int wm = warp >> 2, wn = warp & 3;
    int m0 = blockIdx.x * 64;        // tokens
    int n0 = blockIdx.y * 128;       // out channels

    int z = FIN ? 3 : (int)blockIdx.z;
    const __half* W  = g_wh + (size_t)z * (C_DIM * C_DIM);
    const __half* Xt = FIN ? g_aot : (z == 0 ? g_qnt : g_vnt);
    const float* bias = FIN ? b0p : (z == 0 ? b0p : (z == 1 ? b1p : b2p));
    __half* OutH = z == 0 ? g_qt : (z == 1 ? g_kt : g_vt);

    float acc[2][4][4];
    #pragma unroll
    for (int i = 0; i < 2; ++i)
        #pragma unroll
        for (int j = 0; j < 4; ++j)
            #pragma unroll
            for (int r = 0; r < 4; ++r) acc[i][j][r] = 0.f;

    #define GLOAD(st, k0)                                                        \
    {                                                                            \
        { int m = tid >> 2, q = tid & 3;                                         \
          cp16(&As[st][m * 40 + q * 8], &Xt[(size_t)(m0 + m) * 512 + (k0) + q * 8]); } \
        _Pragma("unroll")                                                        \
        for (int i = 0; i < 2; ++i) {                                            \
            int idx = tid + i * 256; int n = idx >> 2, q = idx & 3;              \
            cp16(&Bs[st][n * 40 + q * 8], &W[(size_t)(n0 + n) * 512 + (k0) + q * 8]); \
        }                                                                        \
    }

    GLOAD(0, 0); CP_COMMIT;

    #pragma unroll 1
    for (int kt = 0; kt < 16; ++kt) {
        int s = kt & 1;
        if (kt < 15) { GLOAD(s ^ 1, (kt + 1) * 32); CP_COMMIT; CP_WAIT1; }
        else         { CP_WAIT0; }
        __syncthreads();

        const unsigned* Au = (const unsigned*)As[s];
        const unsigned* Bu = (const unsigned*)Bs[s];
        #pragma unroll
        for (int kk = 0; kk < 2; ++kk) {
            unsigned a[2][4], b[4][2];
            #pragma unroll
            for (int mi = 0; mi < 2; ++mi) {
                int r = wm * 32 + mi * 16 + g;
                a[mi][0] = Au[r * 20 + kk * 8 + qq];
                a[mi][1] = Au[(r + 8) * 20 + kk * 8 + qq];
                a[mi][2] = Au[r * 20 + kk * 8 + qq + 4];
                a[mi][3] = Au[(r + 8) * 20 + kk * 8 + qq + 4];
            }
            #pragma unroll
            for (int ni = 0; ni < 4; ++ni) {
                int n = wn * 32 + ni * 8 + g;
                b[ni][0] = Bu[n * 20 + kk * 8 + qq];
                b[ni][1] = Bu[n * 20 + kk * 8 + qq + 4];
            }
            #pragma unroll
            for (int mi = 0; mi < 2; ++mi)
                #pragma unroll
                for (int ni = 0; ni < 4; ++ni)
                    mma16816(acc[mi][ni], a[mi], b[ni][0], b[ni][1]);
        }
        __syncthreads();
    }
    #undef GLOAD

    const float IS2 = 0.70710678118654752f;
    float bscale = (!FIN && z == 0) ? ALPHA : 1.f;
    #pragma unroll
    for (int mi = 0; mi < 2; ++mi) {
        int t = m0 + wm * 32 + mi * 16 + g;
        #pragma unroll
        for (int ni = 0; ni < 4; ++ni) {
            int ch = n0 + wn * 32 + ni * 8 + 2 * qq;
            float bb0 = bias[ch] * bscale, bb1 = bias[ch + 1] * bscale;
            float c0 = acc[mi][ni][0] + bb0, c1 = acc[mi][ni][1] + bb1;
            float c2 = acc[mi][ni][2] + bb0, c3 = acc[mi][ni][3] + bb1;
            if (FIN) {
                size_t i00 = (size_t)ch * N_TOK + t;
                size_t i10 = (size_t)(ch + 1) * N_TOK + t;
                OutF[i00]     = (c0 + resid[i00])     * IS2;
                OutF[i10]     = (c1 + resid[i10])     * IS2;
                OutF[i00 + 8] = (c2 + resid[i00 + 8]) * IS2;
                OutF[i10 + 8] = (c3 + resid[i10 + 8]) * IS2;
            } else {
                *(unsigned*)&OutH[(size_t)t * 512 + ch]       = packh2(c0, c1);
                *(unsigned*)&OutH[(size_t)(t + 8) * 512 + ch] = packh2(c2, c3);
            }
        }
    }
}

// ---------------------------------------------------------------------------
// Flash attention fp16: CTA = 128 queries x head, 8 warps x 16 q-rows.
// 64-key tiles; P in registers; exp via ex2.approx.f16x2; l via ones-MMA.
// ---------------------------------------------------------------------------
__global__ __launch_bounds__(256, 2) void attn_h() {
    __shared__ __half Ks[2][64 * 40];
    __shared__ __half Vs[2][64 * 40];

    int tid = threadIdx.x;
    int lane = tid & 31;
    int w = tid >> 5;
    int g = lane >> 2, qq = lane & 3;
    int h = blockIdx.y;
    int hb = h * HDIM;
    int q0 = blockIdx.x * 128 + w * 16;

    unsigned qa[2][4];
    #pragma unroll
    for (int kk = 0; kk < 2; ++kk) {
        const __half* qp = &g_qt[(size_t)(q0 + g) * 512 + hb + kk * 16 + 2 * qq];
        qa[kk][0] = *(const unsigned*)qp;
        qa[kk][1] = *(const unsigned*)(qp + 8 * 512);
        qa[kk][2] = *(const unsigned*)(qp + 8);
        qa[kk][3] = *(const unsigned*)(qp + 8 * 512 + 8);
    }

    float o[4][4];
    #pragma unroll
    for (int nd = 0; nd < 4; ++nd)
        #pragma unroll
        for (int e = 0; e < 4; ++e) o[nd][e] = 0.f;
    float m0 = -1e30f, m1 = -1e30f, l0 = 0.f, l1 = 0.f;

    int lrow = tid >> 2, lq = tid & 3;

    #define APRE(st, kt0)                                                        \
    {                                                                            \
        cp16(&Ks[st][lrow * 40 + lq * 8],                                        \
             &g_kt[(size_t)((kt0) + lrow) * 512 + hb + lq * 8]);                 \
        cp16(&Vs[st][lrow * 40 + lq * 8],                                        \
             &g_vt[(size_t)((kt0) + lrow) * 512 + hb + lq * 8]);                 \
    }

    APRE(0, 0); CP_COMMIT;

    #pragma unroll 1
    for (int it = 0; it < 64; ++it) {
        int s = it & 1;
        if (it < 63) { APRE(s ^ 1, (it + 1) * 64); CP_COMMIT; CP_WAIT1; }
        else         { CP_WAIT0; }
        __syncthreads();

        // S = Q K^T (16q x 64k)
        const unsigned* Ku = (const unsigned*)Ks[s];
        float sc[8][4];
        #pragma unroll
        for (int nj = 0; nj < 8; ++nj) {
            sc[nj][0] = sc[nj][1] = sc[nj][2] = sc[nj][3] = 0.f;
            int krow = (nj * 8 + g) * 20;
            #pragma unroll
            for (int kk = 0; kk < 2; ++kk)
                mma16816(sc[nj], qa[kk], Ku[krow + kk * 8 + qq], Ku[krow + kk * 8 + qq + 4]);
        }

        // online softmax (log2 domain)
        float mx0 = -1e30f, mx1 = -1e30f;
        #pragma unroll
        for (int nj = 0; nj < 8; ++nj) {
            mx0 = fmaxf(mx0, fmaxf(sc[nj][0], sc[nj][1]));
            mx1 = fmaxf(mx1, fmaxf(sc[nj][2], sc[nj][3]));
        }
        mx0 = fmaxf(mx0, __shfl_xor_sync(0xffffffffu, mx0, 1));
        mx0 = fmaxf(mx0, __shfl_xor_sync(0xffffffffu, mx0, 2));
        mx1 = fmaxf(mx1, __shfl_xor_sync(0xffffffffu, mx1, 1));
        mx1 = fmaxf(mx1, __shfl_xor_sync(0xffffffffu, mx1, 2));
        float nm0 = fmaxf(m0, mx0), nm1 = fmaxf(m1, mx1);
        float cr0 = ex2(m0 - nm0), cr1 = ex2(m1 - nm1);
        m0 = nm0; m1 = nm1;
        #pragma unroll
        for (int nd = 0; nd < 4; ++nd) {
            o[nd][0] *= cr0; o[nd][1] *= cr0;
            o[nd][2] *= cr1; o[nd][3] *= cr1;
        }

        // P = exp2(S - m) computed directly in f16x2 (halves MUFU work);
        // result IS the PV A-fragment.
        unsigned ph[4][4];
        #pragma unroll
        for (int kk = 0; kk < 4; ++kk) {
            ph[kk][0] = h2ex2(packh2(sc[2*kk][0]   - nm0, sc[2*kk][1]   - nm0));
            ph[kk][1] = h2ex2(packh2(sc[2*kk][2]   - nm1, sc[2*kk][3]   - nm1));
            ph[kk][2] = h2ex2(packh2(sc[2*kk+1][0] - nm0, sc[2*kk+1][1] - nm0));
            ph[kk][3] = h2ex2(packh2(sc[2*kk+1][2] - nm1, sc[2*kk+1][3] - nm1));
        }

        // l row-sums via ones-MMA (exact fp32, consistent with fp16 P)
        float lacc[4] = {0.f, 0.f, 0.f, 0.f};
        #pragma unroll
        for (int kk = 0; kk < 4; ++kk)
            mma16816(lacc, ph[kk], ONESH2, ONESH2);
        l0 = l0 * cr0 + lacc[0];
        l1 = l1 * cr1 + lacc[2];

        // O += P V
        int vr = (lane & 15) * 40 + ((lane >> 4) << 3);
        #pragma unroll
        for (int kk = 0; kk < 4; ++kk) {
            unsigned v0[4], v1[4];
            ldsm4t(v0, &Vs[s][kk * 16 * 40 + vr]);
            ldsm4t(v1, &Vs[s][kk * 16 * 40 + vr + 16]);
            mma16816(o[0], ph[kk], v0[0], v0[1]);
            mma16816(o[1], ph[kk], v0[2], v0[3]);
            mma16816(o[2], ph[kk], v1[0], v1[1]);
            mma16816(o[3], ph[kk], v1[2], v1[3]);
        }
        __syncthreads();
    }
    #undef APRE

    // l0/l1 are complete row sums (ones-MMA) — no final reduction needed.
    float i0 = 1.f / l0, i1 = 1.f / l1;

    #pragma unroll
    for (int nd = 0; nd < 4; ++nd) {
        int d = hb + nd * 8 + 2 * qq;
        *(unsigned*)&g_aot[(size_t)(q0 + g) * 512 + d]     = packh2(o[nd][0] * i0, o[nd][1] * i0);
        *(unsigned*)&g_aot[(size_t)(q0 + g + 8) * 512 + d] = packh2(o[nd][2] * i1, o[nd][3] * i1);
    }
}

// ---------------------------------------------------------------------------
// Launch
// ---------------------------------------------------------------------------
extern "C" void kernel_launch(void* const* d_in, const int* in_sizes, int n_in,
                              void* d_out, int out_size) {
    const float* x   = (const float*)d_in[0];
    const float* gnw = (const float*)d_in[1];
    const float* gnb = (const float*)d_in[2];
    const float* wq  = (const float*)d_in[3];
    const float* bq  = (const float*)d_in[4];
    const float* wk  = (const float*)d_in[5];
    const float* bk  = (const float*)d_in[6];
    const float* wv  = (const float*)d_in[7];
    const float* bv  = (const float*)d_in[8];
    const float* wo  = (const float*)d_in[9];
    const float* bo  = (const float*)d_in[10];
    float* out = (float*)d_out;

    chan_stats<<<C_DIM, 256>>>(x);
    gn_finalize<<<1, 32>>>(gnw, gnb);
    dim3 at(N_TOK / 64, 4);
    apply_tr<<<at, 256>>>(x);
    round_wh<<<512, 256>>>(wq, wk, wv, wo);

    dim3 gqkv(N_TOK / 64, C_DIM / 128, 3);      // (64, 4, 3) = 768
    gemm_h<0><<<gqkv, 256>>>(bq, bk, bv, nullptr, nullptr);

    dim3 ag(N_TOK / 128, HEADS);                // (32, 16)
    attn_h<<<ag, 256>>>();

    dim3 go(N_TOK / 64, C_DIM / 128, 1);        // (64, 4) = 256
    gemm_h<1><<<go, 256>>>(bo, nullptr, nullptr, x, out);
}

// round 7
// speedup vs baseline: 6.9601x; 1.0136x over previous
#include <cuda_runtime.h>
#include <cuda_fp16.h>

#define C_DIM 512
#define N_TOK 4096
#define HEADS 16
#define HDIM  32
// (1/sqrt(32)) * log2(e), folded into wq/bq
#define ALPHA 0.25504448f
#define ONESH2 0x3C003C00u

// ---------------- scratch ----------------
__device__ __half g_qnt[N_TOK * C_DIM];
__device__ __half g_vnt[N_TOK * C_DIM];
__device__ __half g_qt [N_TOK * C_DIM];
__device__ __half g_kt [N_TOK * C_DIM];
__device__ __half g_vt [N_TOK * C_DIM];
__device__ __half g_aot[N_TOK * C_DIM];
__device__ __half g_wh [4 * C_DIM * C_DIM];
__device__ float g_cs[C_DIM], g_cq[C_DIM];

// ---------------- helpers ----------------
__device__ __forceinline__ float ex2(float x) {
    float r; asm("ex2.approx.ftz.f32 %0, %1;" : "=f"(r) : "f"(x)); return r;
}
__device__ __forceinline__ unsigned h2ex2(unsigned x) {
    unsigned r; asm("ex2.approx.f16x2 %0, %1;" : "=r"(r) : "r"(x)); return r;
}
__device__ __forceinline__ unsigned packh2(float lo, float hi) {
    unsigned u; asm("cvt.rn.f16x2.f32 %0, %1, %2;" : "=r"(u) : "f"(hi), "f"(lo)); return u;
}
__device__ __forceinline__ void mma16816(float* d, const unsigned* a, unsigned b0, unsigned b1) {
    asm volatile(
        "mma.sync.aligned.m16n8k16.row.col.f32.f16.f16.f32 "
        "{%0,%1,%2,%3}, {%4,%5,%6,%7}, {%8,%9}, {%0,%1,%2,%3};"
        : "+f"(d[0]), "+f"(d[1]), "+f"(d[2]), "+f"(d[3])
        : "r"(a[0]), "r"(a[1]), "r"(a[2]), "r"(a[3]), "r"(b0), "r"(b1));
}
__device__ __forceinline__ void ldsm4(unsigned* r, const void* p) {
    unsigned a = (unsigned)__cvta_generic_to_shared(p);
    asm volatile("ldmatrix.sync.aligned.m8n8.x4.shared.b16 {%0,%1,%2,%3}, [%4];"
                 : "=r"(r[0]), "=r"(r[1]), "=r"(r[2]), "=r"(r[3]) : "r"(a));
}
__device__ __forceinline__ void ldsm4t(unsigned* r, const void* p) {
    unsigned a = (unsigned)__cvta_generic_to_shared(p);
    asm volatile("ldmatrix.sync.aligned.m8n8.x4.trans.shared.b16 {%0,%1,%2,%3}, [%4];"
                 : "=r"(r[0]), "=r"(r[1]), "=r"(r[2]), "=r"(r[3]) : "r"(a));
}
__device__ __forceinline__ void cp16(void* smem, const void* gmem) {
    unsigned sa = (unsigned)__cvta_generic_to_shared(smem);
    asm volatile("cp.async.cg.shared.global [%0], [%1], 16;" :: "r"(sa), "l"(gmem) : "memory");
}
#define CP_COMMIT asm volatile("cp.async.commit_group;" ::: "memory")
#define CP_WAIT1  asm volatile("cp.async.wait_group 1;" ::: "memory")
#define CP_WAIT0  asm volatile("cp.async.wait_group 0;" ::: "memory")

// ---------------------------------------------------------------------------
// Fused: per-channel stats (blocks 0..511) + weight fp16 rounding (512..1023).
// ---------------------------------------------------------------------------
__global__ __launch_bounds__(256) void stats_weights(const float* __restrict__ x,
                                                     const float* __restrict__ wq,
                                                     const float* __restrict__ wk,
                                                     const float* __restrict__ wv,
                                                     const float* __restrict__ wo) {
    int b = blockIdx.x;
    if (b < C_DIM) {
        __shared__ float sh[16];
        const float4* p = (const float4*)(x + (size_t)b * N_TOK);
        float s = 0.f, sq = 0.f;
        #pragma unroll
        for (int i = threadIdx.x; i < N_TOK / 4; i += 256) {
            float4 v = p[i];
            s  += (v.x + v.y) + (v.z + v.w);
            sq += v.x * v.x + v.y * v.y + v.z * v.z + v.w * v.w;
        }
        #pragma unroll
        for (int off = 16; off > 0; off >>= 1) {
            s  += __shfl_down_sync(0xffffffffu, s,  off);
            sq += __shfl_down_sync(0xffffffffu, sq, off);
        }
        int wr = threadIdx.x >> 5, lane = threadIdx.x & 31;
        if (lane == 0) { sh[wr] = s; sh[8 + wr] = sq; }
        __syncthreads();
        if (threadIdx.x == 0) {
            float ts = 0.f, tq = 0.f;
            #pragma unroll
            for (int i = 0; i < 8; ++i) { ts += sh[i]; tq += sh[8 + i]; }
            g_cs[b] = ts; g_cq[b] = tq;
        }
    } else {
        // weights -> fp16 (wq scaled by ALPHA); 512 float4 per block
        int base = (b - C_DIM) * 512;
        #pragma unroll
        for (int it = 0; it < 2; ++it) {
            int i = base + threadIdx.x + it * 256;
            int sel = i >> 16, loc = i & 65535;
            const float4* src = (const float4*)(sel == 0 ? wq : sel == 1 ? wk : sel == 2 ? wv : wo);
            float sc = (sel == 0) ? ALPHA : 1.f;
            float4 v = src[loc];
            uint2 o;
            o.x = packh2(v.x * sc, v.y * sc);
            o.y = packh2(v.z * sc, v.w * sc);
            *(uint2*)&g_wh[(size_t)i * 4] = o;
        }
    }
}

// ---------------------------------------------------------------------------
// GN apply + transpose, with inline finalize (each block derives both GN
// affines analytically from g_cs/g_cq). x[c][n] -> qnt/vnt token-major fp16.
// grid (N_TOK/64, 4)
// ---------------------------------------------------------------------------
__global__ __launch_bounds__(256) void apply_tr(const float* __restrict__ x,
                                                const float* __restrict__ w,
                                                const float* __restrict__ b) {
    __shared__ float a1s[C_DIM], c1s[C_DIM], avs[C_DIM], cvs[C_DIM];
    __shared__ __half sq[64][132];
    __shared__ __half sv[64][132];
    int tid = threadIdx.x;

    if (tid < 32) {
        int g = tid;
        const float inv = 1.f / (float)N_TOK;
        float m1 = 0.f, E1 = 0.f;
        #pragma unroll
        for (int c = 0; c < 16; ++c) {
            int ch = g * 16 + c;
            m1 += g_cs[ch] * inv;
            E1 += g_cq[ch] * inv;
        }
        m1 *= (1.f / 16.f); E1 *= (1.f / 16.f);
        float is1 = rsqrtf(E1 - m1 * m1 + 1e-6f);
        float m2 = 0.f, E2 = 0.f;
        #pragma unroll
        for (int c = 0; c < 16; ++c) {
            int ch = g * 16 + c;
            float mc = g_cs[ch] * inv, Ec = g_cq[ch] * inv;
            float a1 = w[ch] * is1;
            float c1 = b[ch] - m1 * a1;
            a1s[ch] = a1; c1s[ch] = c1;
            m2 += a1 * mc + c1;
            E2 += a1 * a1 * Ec + 2.f * a1 * c1 * mc + c1 * c1;
        }
        m2 *= (1.f / 16.f); E2 *= (1.f / 16.f);
        float is2 = rsqrtf(E2 - m2 * m2 + 1e-6f);
        #pragma unroll
        for (int c = 0; c < 16; ++c) {
            int ch = g * 16 + c;
            float a2 = w[ch] * is2;
            float c2 = b[ch] - m2 * a2;
            avs[ch] = a2 * a1s[ch];
            cvs[ch] = a2 * c1s[ch] + c2;
        }
    }
    __syncthreads();

    int n0 = blockIdx.x * 64;
    int cc = blockIdx.y;
    #pragma unroll
    for (int i = 0; i < 32; ++i) {
        int idx = tid + i * 256;
        int t = idx & 63, ci = idx >> 6;
        int c = cc * 128 + ci;
        float v = x[(size_t)c * N_TOK + n0 + t];
        sq[t][ci] = __float2half_rn(v * a1s[c] + c1s[c]);
        sv[t][ci] = __float2half_rn(v * avs[c] + cvs[c]);
    }
    __syncthreads();
    #pragma unroll
    for (int i = 0; i < 16; ++i) {
        int idx = tid + i * 256;
        int t = idx >> 6, j = idx & 63;
        __half2 q2 = __halves2half2(sq[t][2 * j], sq[t][2 * j + 1]);
        __half2 v2 = __halves2half2(sv[t][2 * j], sv[t][2 * j + 1]);
        *(__half2*)&g_qnt[(size_t)(n0 + t) * 512 + cc * 128 + 2 * j] = q2;
        *(__half2*)&g_vnt[(size_t)(n0 + t) * 512 + cc * 128 + 2 * j] = v2;
    }
}

// ---------------------------------------------------------------------------
// fp16 GEMM (unchanged from round 5): C[tok][outch] = Xt * W^T + bias.
// ---------------------------------------------------------------------------
template<int FIN>
__global__ __launch_bounds__(256, 2) void gemm_h(const float* __restrict__ b0p,
                                                 const float* __restrict__ b1p,
                                                 const float* __restrict__ b2p,
                                                 const float* __restrict__ resid,
                                                 float* __restrict__ OutF) {
    __shared__ __half As[2][64 * 40];
    __shared__ __half Bs[2][128 * 40];

    int tid = threadIdx.x;
    int warp = tid >> 5, lane = tid & 31;
    int g = lane >> 2, qq = lane & 3;
    int wm = warp >> 2, wn = warp & 3;
    int m0 = blockIdx.x * 64;
    int n0 = blockIdx.y * 128;

    int z = FIN ? 3 : (int)blockIdx.z;
    const __half* W  = g_wh + (size_t)z * (C_DIM * C_DIM);
    const __half* Xt = FIN ? g_aot : (z == 0 ? g_qnt : g_vnt);
    const float* bias = FIN ? b0p : (z == 0 ? b0p : (z == 1 ? b1p : b2p));
    __half* OutH = z == 0 ? g_qt : (z == 1 ? g_kt : g_vt);

    float acc[2][4][4];
    #pragma unroll
    for (int i = 0; i < 2; ++i)
        #pragma unroll
        for (int j = 0; j < 4; ++j)
            #pragma unroll
            for (int r = 0; r < 4; ++r) acc[i][j][r] = 0.f;

    #define GLOAD(st, k0)                                                        \
    {                                                                            \
        { int m = tid >> 2, q = tid & 3;                                         \
          cp16(&As[st][m * 40 + q * 8], &Xt[(size_t)(m0 + m) * 512 + (k0) + q * 8]); } \
        _Pragma("unroll")                                                        \
        for (int i = 0; i < 2; ++i) {                                            \
            int idx = tid + i * 256; int n = idx >> 2, q = idx & 3;              \
            cp16(&Bs[st][n * 40 + q * 8], &W[(size_t)(n0 + n) * 512 + (k0) + q * 8]); \
        }                                                                        \
    }

    GLOAD(0, 0); CP_COMMIT;

    #pragma unroll 1
    for (int kt = 0; kt < 16; ++kt) {
        int s = kt & 1;
        if (kt < 15) { GLOAD(s ^ 1, (kt + 1) * 32); CP_COMMIT; CP_WAIT1; }
        else         { CP_WAIT0; }
        __syncthreads();

        const unsigned* Au = (const unsigned*)As[s];
        const unsigned* Bu = (const unsigned*)Bs[s];
        #pragma unroll
        for (int kk = 0; kk < 2; ++kk) {
            unsigned a[2][4], bb[4][2];
            #pragma unroll
            for (int mi = 0; mi < 2; ++mi) {
                int r = wm * 32 + mi * 16 + g;
                a[mi][0] = Au[r * 20 + kk * 8 + qq];
                a[mi][1] = Au[(r + 8) * 20 + kk * 8 + qq];
                a[mi][2] = Au[r * 20 + kk * 8 + qq + 4];
                a[mi][3] = Au[(r + 8) * 20 + kk * 8 + qq + 4];
            }
            #pragma unroll
            for (int ni = 0; ni < 4; ++ni) {
                int n = wn * 32 + ni * 8 + g;
                bb[ni][0] = Bu[n * 20 + kk * 8 + qq];
                bb[ni][1] = Bu[n * 20 + kk * 8 + qq + 4];
            }
            #pragma unroll
            for (int mi = 0; mi < 2; ++mi)
                #pragma unroll
                for (int ni = 0; ni < 4; ++ni)
                    mma16816(acc[mi][ni], a[mi], bb[ni][0], bb[ni][1]);
        }
        __syncthreads();
    }
    #undef GLOAD

    const float IS2 = 0.70710678118654752f;
    float bscale = (!FIN && z == 0) ? ALPHA : 1.f;
    #pragma unroll
    for (int mi = 0; mi < 2; ++mi) {
        int t = m0 + wm * 32 + mi * 16 + g;
        #pragma unroll
        for (int ni = 0; ni < 4; ++ni) {
            int ch = n0 + wn * 32 + ni * 8 + 2 * qq;
            float bb0 = bias[ch] * bscale, bb1 = bias[ch + 1] * bscale;
            float c0 = acc[mi][ni][0] + bb0, c1 = acc[mi][ni][1] + bb1;
            float c2 = acc[mi][ni][2] + bb0, c3 = acc[mi][ni][3] + bb1;
            if (FIN) {
                size_t i00 = (size_t)ch * N_TOK + t;
                size_t i10 = (size_t)(ch + 1) * N_TOK + t;
                OutF[i00]     = (c0 + resid[i00])     * IS2;
                OutF[i10]     = (c1 + resid[i10])     * IS2;
                OutF[i00 + 8] = (c2 + resid[i00 + 8]) * IS2;
                OutF[i10 + 8] = (c3 + resid[i10 + 8]) * IS2;
            } else {
                *(unsigned*)&OutH[(size_t)t * 512 + ch]       = packh2(c0, c1);
                *(unsigned*)&OutH[(size_t)(t + 8) * 512 + ch] = packh2(c2, c3);
            }
        }
    }
}

// ---------------------------------------------------------------------------
// Flash attention fp16: CTA = 128 queries x head, 8 warps x 16 q-rows.
// 128-key tiles; K frags via ldmatrix.x4; P in regs; f16x2 exp; ones-MMA l.
// ---------------------------------------------------------------------------
__global__ __launch_bounds__(256, 2) void attn_h() {
    __shared__ __half Ks[2][128 * 40];
    __shared__ __half Vs[2][128 * 40];

    int tid = threadIdx.x;
    int lane = tid & 31;
    int w = tid >> 5;
    int g = lane >> 2, qq = lane & 3;
    int h = blockIdx.y;
    int hb = h * HDIM;
    int q0 = blockIdx.x * 128 + w * 16;

    unsigned qa[2][4];
    #pragma unroll
    for (int kk = 0; kk < 2; ++kk) {
        const __half* qp = &g_qt[(size_t)(q0 + g) * 512 + hb + kk * 16 + 2 * qq];
        qa[kk][0] = *(const unsigned*)qp;
        qa[kk][1] = *(const unsigned*)(qp + 8 * 512);
        qa[kk][2] = *(const unsigned*)(qp + 8);
        qa[kk][3] = *(const unsigned*)(qp + 8 * 512 + 8);
    }

    float o[4][4];
    #pragma unroll
    for (int nd = 0; nd < 4; ++nd)
        #pragma unroll
        for (int e = 0; e < 4; ++e) o[nd][e] = 0.f;
    float m0 = -1e30f, m1 = -1e30f, l0 = 0.f, l1 = 0.f;

    // ldmatrix source offsets
    int kfrag = (lane & 7) * 40 + ((lane >> 3) << 3);          // QK B-frags
    int vfrag = (lane & 15) * 40 + ((lane >> 4) << 3);         // PV B-frags (trans)

    #define APRE(st, kt0)                                                        \
    {                                                                            \
        _Pragma("unroll")                                                        \
        for (int i = 0; i < 2; ++i) {                                            \
            int idx = tid + i * 256; int row = idx >> 2, q = idx & 3;            \
            cp16(&Ks[st][row * 40 + q * 8],                                      \
                 &g_kt[(size_t)((kt0) + row) * 512 + hb + q * 8]);               \
            cp16(&Vs[st][row * 40 + q * 8],                                      \
                 &g_vt[(size_t)((kt0) + row) * 512 + hb + q * 8]);               \
        }                                                                        \
    }

    APRE(0, 0); CP_COMMIT;

    #pragma unroll 1
    for (int it = 0; it < 32; ++it) {
        int s = it & 1;
        if (it < 31) { APRE(s ^ 1, (it + 1) * 128); CP_COMMIT; CP_WAIT1; }
        else         { CP_WAIT0; }
        __syncthreads();

        // S = Q K^T (16q x 128k); K B-frags via ldmatrix.x4
        float sc[16][4];
        #pragma unroll
        for (int nj = 0; nj < 16; ++nj) {
            unsigned kb[4];
            ldsm4(kb, &Ks[s][nj * 8 * 40 + kfrag]);
            sc[nj][0] = sc[nj][1] = sc[nj][2] = sc[nj][3] = 0.f;
            mma16816(sc[nj], qa[0], kb[0], kb[1]);
            mma16816(sc[nj], qa[1], kb[2], kb[3]);
        }

        // row max (rows g and g+8), quad-lane reduce
        float mx0 = -1e30f, mx1 = -1e30f;
        #pragma unroll
        for (int nj = 0; nj < 16; ++nj) {
            mx0 = fmaxf(mx0, fmaxf(sc[nj][0], sc[nj][1]));
            mx1 = fmaxf(mx1, fmaxf(sc[nj][2], sc[nj][3]));
        }
        mx0 = fmaxf(mx0, __shfl_xor_sync(0xffffffffu, mx0, 1));
        mx0 = fmaxf(mx0, __shfl_xor_sync(0xffffffffu, mx0, 2));
        mx1 = fmaxf(mx1, __shfl_xor_sync(0xffffffffu, mx1, 1));
        mx1 = fmaxf(mx1, __shfl_xor_sync(0xffffffffu, mx1, 2));
        float nm0 = fmaxf(m0, mx0), nm1 = fmaxf(m1, mx1);
        float cr0 = ex2(m0 - nm0), cr1 = ex2(m1 - nm1);
        m0 = nm0; m1 = nm1;
        #pragma unroll
        for (int nd = 0; nd < 4; ++nd) {
            o[nd][0] *= cr0; o[nd][1] *= cr0;
            o[nd][2] *= cr1; o[nd][3] *= cr1;
        }

        // per 16-key block: P = exp2(S - m) in f16x2, l-MMA, PV
        float lacc[4] = {0.f, 0.f, 0.f, 0.f};
        #pragma unroll
        for (int kk = 0; kk < 8; ++kk) {
            unsigned ph[4];
            ph[0] = h2ex2(packh2(sc[2*kk][0]   - nm0, sc[2*kk][1]   - nm0));
            ph[1] = h2ex2(packh2(sc[2*kk][2]   - nm1, sc[2*kk][3]   - nm1));
            ph[2] = h2ex2(packh2(sc[2*kk+1][0] - nm0, sc[2*kk+1][1] - nm0));
            ph[3] = h2ex2(packh2(sc[2*kk+1][2] - nm1, sc[2*kk+1][3] - nm1));
            mma16816(lacc, ph, ONESH2, ONESH2);
            unsigned v0[4], v1[4];
            int vb = kk * 16 * 40 + vfrag;
            ldsm4t(v0, &Vs[s][vb]);
            ldsm4t(v1, &Vs[s][vb + 16]);
            mma16816(o[0], ph, v0[0], v0[1]);
            mma16816(o[1], ph, v0[2], v0[3]);
            mma16816(o[2], ph, v1[0], v1[1]);
            mma16816(o[3], ph, v1[2], v1[3]);
        }
        l0 = l0 * cr0 + lacc[0];
        l1 = l1 * cr1 + lacc[2];
        __syncthreads();
    }
    #undef APRE

    float i0 = 1.f / l0, i1 = 1.f / l1;
    #pragma unroll
    for (int nd = 0; nd < 4; ++nd) {
        int d = hb + nd * 8 + 2 * qq;
        *(unsigned*)&g_aot[(size_t)(q0 + g) * 512 + d]     = packh2(o[nd][0] * i0, o[nd][1] * i0);
        *(unsigned*)&g_aot[(size_t)(q0 + g + 8) * 512 + d] = packh2(o[nd][2] * i1, o[nd][3] * i1);
    }
}

// ---------------------------------------------------------------------------
// Launch
// ---------------------------------------------------------------------------
extern "C" void kernel_launch(void* const* d_in, const int* in_sizes, int n_in,
                              void* d_out, int out_size) {
    const float* x   = (const float*)d_in[0];
    const float* gnw = (const float*)d_in[1];
    const float* gnb = (const float*)d_in[2];
    const float* wq  = (const float*)d_in[3];
    const float* bq  = (const float*)d_in[4];
    const float* wk  = (const float*)d_in[5];
    const float* bk  = (const float*)d_in[6];
    const float* wv  = (const float*)d_in[7];
    const float* bv  = (const float*)d_in[8];
    const float* wo  = (const float*)d_in[9];
    const float* bo  = (const float*)d_in[10];
    float* out = (float*)d_out;

    stats_weights<<<1024, 256>>>(x, wq, wk, wv, wo);

    dim3 at(N_TOK / 64, 4);
    apply_tr<<<at, 256>>>(x, gnw, gnb);

    dim3 gqkv(N_TOK / 64, C_DIM / 128, 3);      // 768 CTAs
    gemm_h<0><<<gqkv, 256>>>(bq, bk, bv, nullptr, nullptr);

    dim3 ag(N_TOK / 128, HEADS);                // (32, 16)
    attn_h<<<ag, 256>>>();

    dim3 go(N_TOK / 64, C_DIM / 128, 1);        // 256 CTAs
    gemm_h<1><<<go, 256>>>(bo, nullptr, nullptr, x, out);
}

// round 10
// speedup vs baseline: 7.5775x; 1.0887x over previous
#include <cuda_runtime.h>
#include <cuda_fp16.h>

#define C_DIM 512
#define N_TOK 4096
#define HEADS 16
#define HDIM  32
// (1/sqrt(32)) * log2(e), folded into wq/bq
#define ALPHA 0.25504448f
#define ONESH2 0x3C003C00u

// ---------------- scratch ----------------
__device__ __half g_qnt[N_TOK * C_DIM];
__device__ __half g_vnt[N_TOK * C_DIM];
__device__ __half g_qt [N_TOK * C_DIM];
__device__ __half g_kt [N_TOK * C_DIM];
__device__ __half g_vt [N_TOK * C_DIM];
__device__ __half g_aot[N_TOK * C_DIM];
__device__ __half g_wh [4 * C_DIM * C_DIM];
__device__ float g_cs[C_DIM], g_cq[C_DIM];

// ---------------- helpers ----------------
__device__ __forceinline__ float ex2(float x) {
    float r; asm("ex2.approx.ftz.f32 %0, %1;" : "=f"(r) : "f"(x)); return r;
}
__device__ __forceinline__ unsigned h2ex2(unsigned x) {
    unsigned r; asm("ex2.approx.f16x2 %0, %1;" : "=r"(r) : "r"(x)); return r;
}
__device__ __forceinline__ unsigned packh2(float lo, float hi) {
    unsigned u; asm("cvt.rn.f16x2.f32 %0, %1, %2;" : "=r"(u) : "f"(hi), "f"(lo)); return u;
}
__device__ __forceinline__ unsigned hsub2(unsigned a, unsigned b) {
    unsigned r; asm("sub.rn.f16x2 %0, %1, %2;" : "=r"(r) : "r"(a), "r"(b)); return r;
}
__device__ __forceinline__ void mma16816(float* d, const unsigned* a, unsigned b0, unsigned b1) {
    asm volatile(
        "mma.sync.aligned.m16n8k16.row.col.f32.f16.f16.f32 "
        "{%0,%1,%2,%3}, {%4,%5,%6,%7}, {%8,%9}, {%0,%1,%2,%3};"
        : "+f"(d[0]), "+f"(d[1]), "+f"(d[2]), "+f"(d[3])
        : "r"(a[0]), "r"(a[1]), "r"(a[2]), "r"(a[3]), "r"(b0), "r"(b1));
}
// zero-accumulator form: ptxas maps the 0.0f operands onto RZ (no init MOVs)
__device__ __forceinline__ void mma16816_z(float* d, const unsigned* a, unsigned b0, unsigned b1) {
    asm volatile(
        "mma.sync.aligned.m16n8k16.row.col.f32.f16.f16.f32 "
        "{%0,%1,%2,%3}, {%4,%5,%6,%7}, {%8,%9}, {%10,%10,%10,%10};"
        : "=f"(d[0]), "=f"(d[1]), "=f"(d[2]), "=f"(d[3])
        : "r"(a[0]), "r"(a[1]), "r"(a[2]), "r"(a[3]), "r"(b0), "r"(b1), "f"(0.f));
}
__device__ __forceinline__ unsigned su32(const void* p) {
    return (unsigned)__cvta_generic_to_shared(p);
}
__device__ __forceinline__ void ldsm4u(unsigned* r, unsigned a) {
    asm volatile("ldmatrix.sync.aligned.m8n8.x4.shared.b16 {%0,%1,%2,%3}, [%4];"
                 : "=r"(r[0]), "=r"(r[1]), "=r"(r[2]), "=r"(r[3]) : "r"(a));
}
__device__ __forceinline__ void ldsm4tu(unsigned* r, unsigned a) {
    asm volatile("ldmatrix.sync.aligned.m8n8.x4.trans.shared.b16 {%0,%1,%2,%3}, [%4];"
                 : "=r"(r[0]), "=r"(r[1]), "=r"(r[2]), "=r"(r[3]) : "r"(a));
}
__device__ __forceinline__ void cp16(void* smem, const void* gmem) {
    unsigned sa = (unsigned)__cvta_generic_to_shared(smem);
    asm volatile("cp.async.cg.shared.global [%0], [%1], 16;" :: "r"(sa), "l"(gmem) : "memory");
}
#define CP_COMMIT asm volatile("cp.async.commit_group;" ::: "memory")
#define CP_WAIT1  asm volatile("cp.async.wait_group 1;" ::: "memory")
#define CP_WAIT0  asm volatile("cp.async.wait_group 0;" ::: "memory")

// ---------------------------------------------------------------------------
// Fused: per-channel stats (blocks 0..511) + weight fp16 rounding (512..1023).
// ---------------------------------------------------------------------------
__global__ __launch_bounds__(256) void stats_weights(const float* __restrict__ x,
                                                     const float* __restrict__ wq,
                                                     const float* __restrict__ wk,
                                                     const float* __restrict__ wv,
                                                     const float* __restrict__ wo) {
    int b = blockIdx.x;
    if (b < C_DIM) {
        __shared__ float sh[16];
        const float4* p = (const float4*)(x + (size_t)b * N_TOK);
        float s = 0.f, sq = 0.f;
        #pragma unroll
        for (int i = threadIdx.x; i < N_TOK / 4; i += 256) {
            float4 v = p[i];
            s  += (v.x + v.y) + (v.z + v.w);
            sq += v.x * v.x + v.y * v.y + v.z * v.z + v.w * v.w;
        }
        #pragma unroll
        for (int off = 16; off > 0; off >>= 1) {
            s  += __shfl_down_sync(0xffffffffu, s,  off);
            sq += __shfl_down_sync(0xffffffffu, sq, off);
        }
        int wr = threadIdx.x >> 5, lane = threadIdx.x & 31;
        if (lane == 0) { sh[wr] = s; sh[8 + wr] = sq; }
        __syncthreads();
        if (threadIdx.x == 0) {
            float ts = 0.f, tq = 0.f;
            #pragma unroll
            for (int i = 0; i < 8; ++i) { ts += sh[i]; tq += sh[8 + i]; }
            g_cs[b] = ts; g_cq[b] = tq;
        }
    } else {
        int base = (b - C_DIM) * 512;
        #pragma unroll
        for (int it = 0; it < 2; ++it) {
            int i = base + threadIdx.x + it * 256;
            int sel = i >> 16, loc = i & 65535;
            const float4* src = (const float4*)(sel == 0 ? wq : sel == 1 ? wk : sel == 2 ? wv : wo);
            float sc = (sel == 0) ? ALPHA : 1.f;
            float4 v = src[loc];
            uint2 o;
            o.x = packh2(v.x * sc, v.y * sc);
            o.y = packh2(v.z * sc, v.w * sc);
            *(uint2*)&g_wh[(size_t)i * 4] = o;
        }
    }
}

// ---------------------------------------------------------------------------
// GN apply + transpose with inline analytic finalize. grid (N_TOK/64, 4)
// ---------------------------------------------------------------------------
__global__ __launch_bounds__(256) void apply_tr(const float* __restrict__ x,
                                                const float* __restrict__ w,
                                                const float* __restrict__ b) {
    __shared__ float a1s[C_DIM], c1s[C_DIM], avs[C_DIM], cvs[C_DIM];
    __shared__ __half sq[64][132];
    __shared__ __half sv[64][132];
    int tid = threadIdx.x;

    if (tid < 32) {
        int g = tid;
        const float inv = 1.f / (float)N_TOK;
        float m1 = 0.f, E1 = 0.f;
        #pragma unroll
        for (int c = 0; c < 16; ++c) {
            int ch = g * 16 + c;
            m1 += g_cs[ch] * inv;
            E1 += g_cq[ch] * inv;
        }
        m1 *= (1.f / 16.f); E1 *= (1.f / 16.f);
        float is1 = rsqrtf(E1 - m1 * m1 + 1e-6f);
        float m2 = 0.f, E2 = 0.f;
        #pragma unroll
        for (int c = 0; c < 16; ++c) {
            int ch = g * 16 + c;
            float mc = g_cs[ch] * inv, Ec = g_cq[ch] * inv;
            float a1 = w[ch] * is1;
            float c1 = b[ch] - m1 * a1;
            a1s[ch] = a1; c1s[ch] = c1;
            m2 += a1 * mc + c1;
            E2 += a1 * a1 * Ec + 2.f * a1 * c1 * mc + c1 * c1;
        }
        m2 *= (1.f / 16.f); E2 *= (1.f / 16.f);
        float is2 = rsqrtf(E2 - m2 * m2 + 1e-6f);
        #pragma unroll
        for (int c = 0; c < 16; ++c) {
            int ch = g * 16 + c;
            float a2 = w[ch] * is2;
            float c2 = b[ch] - m2 * a2;
            avs[ch] = a2 * a1s[ch];
            cvs[ch] = a2 * c1s[ch] + c2;
        }
    }
    __syncthreads();

    int n0 = blockIdx.x * 64;
    int cc = blockIdx.y;
    #pragma unroll
    for (int i = 0; i < 32; ++i) {
        int idx = tid + i * 256;
        int t = idx & 63, ci = idx >> 6;
        int c = cc * 128 + ci;
        float v = x[(size_t)c * N_TOK + n0 + t];
        sq[t][ci] = __float2half_rn(v * a1s[c] + c1s[c]);
        sv[t][ci] = __float2half_rn(v * avs[c] + cvs[c]);
    }
    __syncthreads();
    #pragma unroll
    for (int i = 0; i < 16; ++i) {
        int idx = tid + i * 256;
        int t = idx >> 6, j = idx & 63;
        __half2 q2 = __halves2half2(sq[t][2 * j], sq[t][2 * j + 1]);
        __half2 v2 = __halves2half2(sv[t][2 * j], sv[t][2 * j + 1]);
        *(__half2*)&g_qnt[(size_t)(n0 + t) * 512 + cc * 128 + 2 * j] = q2;
        *(__half2*)&g_vnt[(size_t)(n0 + t) * 512 + cc * 128 + 2 * j] = v2;
    }
}

// ---------------------------------------------------------------------------
// fp16 GEMM: C[tok][outch] = Xt * W^T + bias (unchanged structure).
// ---------------------------------------------------------------------------
template<int FIN>
__global__ __launch_bounds__(256, 2) void gemm_h(const float* __restrict__ b0p,
                                                 const float* __restrict__ b1p,
                                                 const float* __restrict__ b2p,
                                                 const float* __restrict__ resid,
                                                 float* __restrict__ OutF) {
    __shared__ __half As[2][64 * 40];
    __shared__ __half Bs[2][128 * 40];

    int tid = threadIdx.x;
    int warp = tid >> 5, lane = tid & 31;
    int g = lane >> 2, qq = lane & 3;
    int wm = warp >> 2, wn = warp & 3;
    int m0 = blockIdx.x * 64;
    int n0 = blockIdx.y * 128;

    int z = FIN ? 3 : (int)blockIdx.z;
    const __half* W  = g_wh + (size_t)z * (C_DIM * C_DIM);
    const __half* Xt = FIN ? g_aot : (z == 0 ? g_qnt : g_vnt);
    const float* bias = FIN ? b0p : (z == 0 ? b0p : (z == 1 ? b1p : b2p));
    __half* OutH = z == 0 ? g_qt : (z == 1 ? g_kt : g_vt);

    float acc[2][4][4];
    #pragma unroll
    for (int i = 0; i < 2; ++i)
        #pragma unroll
        for (int j = 0; j < 4; ++j)
            #pragma unroll
            for (int r = 0; r < 4; ++r) acc[i][j][r] = 0.f;

    #define GLOAD(st, k0)                                                        \
    {                                                                            \
        { int m = tid >> 2, q = tid & 3;                                         \
          cp16(&As[st][m * 40 + q * 8], &Xt[(size_t)(m0 + m) * 512 + (k0) + q * 8]); } \
        _Pragma("unroll")                                                        \
        for (int i = 0; i < 2; ++i) {                                            \
            int idx = tid + i * 256; int n = idx >> 2, q = idx & 3;              \
            cp16(&Bs[st][n * 40 + q * 8], &W[(size_t)(n0 + n) * 512 + (k0) + q * 8]); \
        }                                                                        \
    }

    GLOAD(0, 0); CP_COMMIT;

    #pragma unroll 1
    for (int kt = 0; kt < 16; ++kt) {
        int s = kt & 1;
        if (kt < 15) { GLOAD(s ^ 1, (kt + 1) * 32); CP_COMMIT; CP_WAIT1; }
        else         { CP_WAIT0; }
        __syncthreads();

        const unsigned* Au = (const unsigned*)As[s];
        const unsigned* Bu = (const unsigned*)Bs[s];
        #pragma unroll
        for (int kk = 0; kk < 2; ++kk) {
            unsigned a[2][4], bb[4][2];
            #pragma unroll
            for (int mi = 0; mi < 2; ++mi) {
                int r = wm * 32 + mi * 16 + g;
                a[mi][0] = Au[r * 20 + kk * 8 + qq];
                a[mi][1] = Au[(r + 8) * 20 + kk * 8 + qq];
                a[mi][2] = Au[r * 20 + kk * 8 + qq + 4];
                a[mi][3] = Au[(r + 8) * 20 + kk * 8 + qq + 4];
            }
            #pragma unroll
            for (int ni = 0; ni < 4; ++ni) {
                int n = wn * 32 + ni * 8 + g;
                bb[ni][0] = Bu[n * 20 + kk * 8 + qq];
                bb[ni][1] = Bu[n * 20 + kk * 8 + qq + 4];
            }
            #pragma unroll
            for (int mi = 0; mi < 2; ++mi)
                #pragma unroll
                for (int ni = 0; ni < 4; ++ni)
                    mma16816(acc[mi][ni], a[mi], bb[ni][0], bb[ni][1]);
        }
        __syncthreads();
    }
    #undef GLOAD

    const float IS2 = 0.70710678118654752f;
    float bscale = (!FIN && z == 0) ? ALPHA : 1.f;
    #pragma unroll
    for (int mi = 0; mi < 2; ++mi) {
        int t = m0 + wm * 32 + mi * 16 + g;
        #pragma unroll
        for (int ni = 0; ni < 4; ++ni) {
            int ch = n0 + wn * 32 + ni * 8 + 2 * qq;
            float bb0 = bias[ch] * bscale, bb1 = bias[ch + 1] * bscale;
            float c0 = acc[mi][ni][0] + bb0, c1 = acc[mi][ni][1] + bb1;
            float c2 = acc[mi][ni][2] + bb0, c3 = acc[mi][ni][3] + bb1;
            if (FIN) {
                size_t i00 = (size_t)ch * N_TOK + t;
                size_t i10 = (size_t)(ch + 1) * N_TOK + t;
                OutF[i00]     = (c0 + resid[i00])     * IS2;
                OutF[i10]     = (c1 + resid[i10])     * IS2;
                OutF[i00 + 8] = (c2 + resid[i00 + 8]) * IS2;
                OutF[i10 + 8] = (c3 + resid[i10 + 8]) * IS2;
            } else {
                *(unsigned*)&OutH[(size_t)t * 512 + ch]       = packh2(c0, c1);
                *(unsigned*)&OutH[(size_t)(t + 8) * 512 + ch] = packh2(c2, c3);
            }
        }
    }
}

// ---------------------------------------------------------------------------
// Flash attention fp16: CTA = 64 queries x head (4 warps x 16 q-rows).
// 128-key tiles; RZ-init MMAs; f16x2 subtract+exp; ones-MMA l; hoisted bases.
// ---------------------------------------------------------------------------
__global__ __launch_bounds__(128, 4) void attn_h() {
    __shared__ __half Ks[2][128 * 40];
    __shared__ __half Vs[2][128 * 40];

    int tid = threadIdx.x;
    int lane = tid & 31;
    int w = tid >> 5;
    int g = lane >> 2, qq = lane & 3;
    int h = blockIdx.y;
    int hb = h * HDIM;
    int q0 = blockIdx.x * 64 + w * 16;

    unsigned qa[2][4];
    #pragma unroll
    for (int kk = 0; kk < 2; ++kk) {
        const __half* qp = &g_qt[(size_t)(q0 + g) * 512 + hb + kk * 16 + 2 * qq];
        qa[kk][0] = *(const unsigned*)qp;
        qa[kk][1] = *(const unsigned*)(qp + 8 * 512);
        qa[kk][2] = *(const unsigned*)(qp + 8);
        qa[kk][3] = *(const unsigned*)(qp + 8 * 512 + 8);
    }

    float o[4][4];
    #pragma unroll
    for (int nd = 0; nd < 4; ++nd)
        #pragma unroll
        for (int e = 0; e < 4; ++e) o[nd][e] = 0.f;
    float m0 = -1e30f, m1 = -1e30f, l0 = 0.f, l1 = 0.f;

    // hoisted ldmatrix smem addresses (bytes)
    int kfrag = ((lane & 7) * 40 + ((lane >> 3) << 3)) * 2;
    int vfrag = ((lane & 15) * 40 + ((lane >> 4) << 3)) * 2;
    unsigned ksu[2] = { su32(&Ks[0][0]) + kfrag, su32(&Ks[1][0]) + kfrag };
    unsigned vsu[2] = { su32(&Vs[0][0]) + vfrag, su32(&Vs[1][0]) + vfrag };

    #define APRE(st, kt0)                                                        \
    {                                                                            \
        _Pragma("unroll")                                                        \
        for (int i = 0; i < 4; ++i) {                                            \
            int idx = tid + i * 128; int row = idx >> 2, q = idx & 3;            \
            cp16(&Ks[st][row * 40 + q * 8],                                      \
                 &g_kt[(size_t)((kt0) + row) * 512 + hb + q * 8]);               \
            cp16(&Vs[st][row * 40 + q * 8],                                      \
                 &g_vt[(size_t)((kt0) + row) * 512 + hb + q * 8]);               \
        }                                                                        \
    }

    APRE(0, 0); CP_COMMIT;

    #pragma unroll 1
    for (int it = 0; it < 32; ++it) {
        int s = it & 1;
        if (it < 31) { APRE(s ^ 1, (it + 1) * 128); CP_COMMIT; CP_WAIT1; }
        else         { CP_WAIT0; }
        __syncthreads();

        // S = Q K^T (16q x 128k), RZ-init accumulators
        float sc[16][4];
        #pragma unroll
        for (int nj = 0; nj < 16; ++nj) {
            unsigned kb[4];
            ldsm4u(kb, ksu[s] + nj * (8 * 40 * 2));
            mma16816_z(sc[nj], qa[0], kb[0], kb[1]);
            mma16816  (sc[nj], qa[1], kb[2], kb[3]);
        }

        // row max (rows g, g+8)
        float mx0 = -1e30f, mx1 = -1e30f;
        #pragma unroll
        for (int nj = 0; nj < 16; ++nj) {
            mx0 = fmaxf(mx0, fmaxf(sc[nj][0], sc[nj][1]));
            mx1 = fmaxf(mx1, fmaxf(sc[nj][2], sc[nj][3]));
        }
        mx0 = fmaxf(mx0, __shfl_xor_sync(0xffffffffu, mx0, 1));
        mx0 = fmaxf(mx0, __shfl_xor_sync(0xffffffffu, mx0, 2));
        mx1 = fmaxf(mx1, __shfl_xor_sync(0xffffffffu, mx1, 1));
        mx1 = fmaxf(mx1, __shfl_xor_sync(0xffffffffu, mx1, 2));
        float nm0 = fmaxf(m0, mx0), nm1 = fmaxf(m1, mx1);
        float cr0 = ex2(m0 - nm0), cr1 = ex2(m1 - nm1);
        m0 = nm0; m1 = nm1;
        #pragma unroll
        for (int nd = 0; nd < 4; ++nd) {
            o[nd][0] *= cr0; o[nd][1] *= cr0;
            o[nd][2] *= cr1; o[nd][3] *= cr1;
        }
        unsigned nm00 = packh2(nm0, nm0), nm11 = packh2(nm1, nm1);

        // per 16-key block: P = exp2(S - m) via f16x2 sub+exp; l-MMA; PV
        float lacc[4];
        #pragma unroll
        for (int kk = 0; kk < 8; ++kk) {
            unsigned ph[4];
            ph[0] = h2ex2(hsub2(packh2(sc[2*kk][0],   sc[2*kk][1]),   nm00));
            ph[1] = h2ex2(hsub2(packh2(sc[2*kk][2],   sc[2*kk][3]),   nm11));
            ph[2] = h2ex2(hsub2(packh2(sc[2*kk+1][0], sc[2*kk+1][1]), nm00));
            ph[3] = h2ex2(hsub2(packh2(sc[2*kk+1][2], sc[2*kk+1][3]), nm11));
            if (kk == 0) mma16816_z(lacc, ph, ONESH2, ONESH2);
            else         mma16816  (lacc, ph, ONESH2, ONESH2);
            unsigned v0[4], v1[4];
            unsigned vb = vsu[s] + kk * (16 * 40 * 2);
            ldsm4tu(v0, vb);
            ldsm4tu(v1, vb + 32);
            mma16816(o[0], ph, v0[0], v0[1]);
            mma16816(o[1], ph, v0[2], v0[3]);
            mma16816(o[2], ph, v1[0], v1[1]);
            mma16816(o[3], ph, v1[2], v1[3]);
        }
        l0 = l0 * cr0 + lacc[0];
        l1 = l1 * cr1 + lacc[2];
        __syncthreads();
    }
    #undef APRE

    float i0 = 1.f / l0, i1 = 1.f / l1;
    #pragma unroll
    for (int nd = 0; nd < 4; ++nd) {
        int d = hb + nd * 8 + 2 * qq;
        *(unsigned*)&g_aot[(size_t)(q0 + g) * 512 + d]     = packh2(o[nd][0] * i0, o[nd][1] * i0);
        *(unsigned*)&g_aot[(size_t)(q0 + g + 8) * 512 + d] = packh2(o[nd][2] * i1, o[nd][3] * i1);
    }
}

// ---------------------------------------------------------------------------
// Launch
// ---------------------------------------------------------------------------
extern "C" void kernel_launch(void* const* d_in, const int* in_sizes, int n_in,
                              void* d_out, int out_size) {
    const float* x   = (const float*)d_in[0];
    const float* gnw = (const float*)d_in[1];
    const float* gnb = (const float*)d_in[2];
    const float* wq  = (const float*)d_in[3];
    const float* bq  = (const float*)d_in[4];
    const float* wk  = (const float*)d_in[5];
    const float* bk  = (const float*)d_in[6];
    const float* wv  = (const float*)d_in[7];
    const float* bv  = (const float*)d_in[8];
    const float* wo  = (const float*)d_in[9];
    const float* bo  = (const float*)d_in[10];
    float* out = (float*)d_out;

    stats_weights<<<1024, 256>>>(x, wq, wk, wv, wo);

    dim3 at(N_TOK / 64, 4);
    apply_tr<<<at, 256>>>(x, gnw, gnb);

    dim3 gqkv(N_TOK / 64, C_DIM / 128, 3);      // 768 CTAs
    gemm_h<0><<<gqkv, 256>>>(bq, bk, bv, nullptr, nullptr);

    dim3 ag(N_TOK / 64, HEADS);                 // (64, 16) = 1024 CTAs
    attn_h<<<ag, 128>>>();

    dim3 go(N_TOK / 64, C_DIM / 128, 1);        // 256 CTAs
    gemm_h<1><<<go, 256>>>(bo, nullptr, nullptr, x, out);
}